// round 6
// baseline (speedup 1.0000x reference)
#include <cuda_runtime.h>
#include <cuda_bf16.h>
#include <cstdint>

// Problem constants
#define VOCAB 96
#define TT 16
#define EE 64
#define HH 4
#define KK 16
#define LL 4
#define BB 16384

#define G 4                 // sequences per CTA
#define ROWS (G*TT)         // 64 activation rows per CTA
#define STR 64              // row stride (floats) for all 64-wide buffers
#define NTHREADS 128

typedef unsigned long long ull;

// ---------- packed f32x2 helpers ----------
__device__ __forceinline__ ull pack2(float x, float y) {
    ull r;
    asm("mov.b64 %0, {%1, %2};" : "=l"(r) : "r"(__float_as_uint(x)), "r"(__float_as_uint(y)));
    return r;
}
__device__ __forceinline__ void unpack2(ull p, float& x, float& y) {
    unsigned int a, b;
    asm("mov.b64 {%0, %1}, %2;" : "=r"(a), "=r"(b) : "l"(p));
    x = __uint_as_float(a); y = __uint_as_float(b);
}
__device__ __forceinline__ void fma2(ull& d, ull a, ull b) {
    asm("fma.rn.f32x2 %0, %1, %2, %3;" : "=l"(d) : "l"(a), "l"(b), "l"(d));
}

// ---------- GEMM [64 x 64] * [64 x 64]: A stride 64, W stride 64 ----------
// 128 threads: rb = tid>>4 (8 rows each), cb = tid&15 (4 cols each).
// epi(r, c0, float4) once per output row-quad.
template <class F>
__device__ __forceinline__ void gemm64(const float* __restrict__ A,
                                       const float* __restrict__ W, F epi) {
    const int tid = threadIdx.x;
    const int cb = tid & 15, rb = tid >> 4;
    ull a01[8], a23[8];
#pragma unroll
    for (int i = 0; i < 8; i++) { a01[i] = 0ull; a23[i] = 0ull; }
    const float* Arow = A + rb * 8 * STR;
    const float* Wp = W + cb * 4;
#pragma unroll 2
    for (int e0 = 0; e0 < 64; e0 += 4) {
        ull w01[4], w23[4];
#pragma unroll
        for (int t = 0; t < 4; t++) {
            float4 w = *reinterpret_cast<const float4*>(Wp + (e0 + t) * 64);
            w01[t] = pack2(w.x, w.y);
            w23[t] = pack2(w.z, w.w);
        }
#pragma unroll
        for (int i = 0; i < 8; i++) {
            float4 a = *reinterpret_cast<const float4*>(Arow + i * STR + e0);
            ull ax;
            ax = pack2(a.x, a.x); fma2(a01[i], w01[0], ax); fma2(a23[i], w23[0], ax);
            ax = pack2(a.y, a.y); fma2(a01[i], w01[1], ax); fma2(a23[i], w23[1], ax);
            ax = pack2(a.z, a.z); fma2(a01[i], w01[2], ax); fma2(a23[i], w23[2], ax);
            ax = pack2(a.w, a.w); fma2(a01[i], w01[3], ax); fma2(a23[i], w23[3], ax);
        }
    }
#pragma unroll
    for (int i = 0; i < 8; i++) {
        float4 v;
        unpack2(a01[i], v.x, v.y);
        unpack2(a23[i], v.z, v.w);
        epi(rb * 8 + i, cb * 4, v);
    }
}

// ---------- GEMM [64 x 64] * [64 x 96] (final projection), W stride 96 ----------
__device__ __forceinline__ void gemm96(const float* __restrict__ A,
                                       const float* __restrict__ W,
                                       const float* __restrict__ bias,
                                       float* __restrict__ outbase) {
    const int tid = threadIdx.x;
    const int cb = tid & 15, rb = tid >> 4;
    const int c0 = cb * 6;
    ull acc[8][3];
#pragma unroll
    for (int i = 0; i < 8; i++)
#pragma unroll
        for (int j = 0; j < 3; j++) acc[i][j] = 0ull;
    const float* Arow = A + rb * 8 * STR;
    const float* Wp = W + c0;
#pragma unroll 2
    for (int e0 = 0; e0 < 64; e0 += 4) {
        ull w[4][3];
#pragma unroll
        for (int t = 0; t < 4; t++) {
            const float* wr = Wp + (e0 + t) * 96;
            float2 wA = *reinterpret_cast<const float2*>(wr + 0);
            float2 wB = *reinterpret_cast<const float2*>(wr + 2);
            float2 wC = *reinterpret_cast<const float2*>(wr + 4);
            w[t][0] = pack2(wA.x, wA.y);
            w[t][1] = pack2(wB.x, wB.y);
            w[t][2] = pack2(wC.x, wC.y);
        }
#pragma unroll
        for (int i = 0; i < 8; i++) {
            float4 a = *reinterpret_cast<const float4*>(Arow + i * STR + e0);
            ull ax;
            ax = pack2(a.x, a.x); fma2(acc[i][0], w[0][0], ax); fma2(acc[i][1], w[0][1], ax); fma2(acc[i][2], w[0][2], ax);
            ax = pack2(a.y, a.y); fma2(acc[i][0], w[1][0], ax); fma2(acc[i][1], w[1][1], ax); fma2(acc[i][2], w[1][2], ax);
            ax = pack2(a.z, a.z); fma2(acc[i][0], w[2][0], ax); fma2(acc[i][1], w[2][1], ax); fma2(acc[i][2], w[2][2], ax);
            ax = pack2(a.w, a.w); fma2(acc[i][0], w[3][0], ax); fma2(acc[i][1], w[3][1], ax); fma2(acc[i][2], w[3][2], ax);
        }
    }
    float2 bA = *reinterpret_cast<const float2*>(bias + c0 + 0);
    float2 bB = *reinterpret_cast<const float2*>(bias + c0 + 2);
    float2 bC = *reinterpret_cast<const float2*>(bias + c0 + 4);
#pragma unroll
    for (int i = 0; i < 8; i++) {
        int r = rb * 8 + i;
        float* orow = outbase + (size_t)r * VOCAB + c0;
        float v0, v1;
        unpack2(acc[i][0], v0, v1);
        *reinterpret_cast<float2*>(orow + 0) = make_float2(v0 + bA.x, v1 + bA.y);
        unpack2(acc[i][1], v0, v1);
        *reinterpret_cast<float2*>(orow + 2) = make_float2(v0 + bB.x, v1 + bB.y);
        unpack2(acc[i][2], v0, v1);
        *reinterpret_cast<float2*>(orow + 4) = make_float2(v0 + bC.x, v1 + bC.y);
    }
}

// ---------- LayerNorm over 64 cols, 2 threads per row, 32 cols each ----------
__device__ __forceinline__ void layer_norm(float* xs, const float* g, const float* b) {
    const int tid = threadIdx.x;
    const int r = tid >> 1, p = tid & 1;
    float* base = xs + r * STR + p * 32;
    float4 v[8];
    float s = 0.f, s2 = 0.f;
#pragma unroll
    for (int j = 0; j < 8; j++) {
        v[j] = *reinterpret_cast<const float4*>(base + j * 4);
        s += v[j].x + v[j].y + v[j].z + v[j].w;
        s2 += v[j].x * v[j].x + v[j].y * v[j].y + v[j].z * v[j].z + v[j].w * v[j].w;
    }
    s  += __shfl_xor_sync(0xffffffffu, s, 1, 2);
    s2 += __shfl_xor_sync(0xffffffffu, s2, 1, 2);
    float mean = s * (1.f / 64.f);
    float var = s2 * (1.f / 64.f) - mean * mean;
    float rstd = rsqrtf(var + 1e-5f);
#pragma unroll
    for (int j = 0; j < 8; j++) {
        int c = p * 32 + j * 4;
        float4 gg = *reinterpret_cast<const float4*>(g + c);
        float4 bb = *reinterpret_cast<const float4*>(b + c);
        float4 o;
        o.x = (v[j].x - mean) * rstd * gg.x + bb.x;
        o.y = (v[j].y - mean) * rstd * gg.y + bb.y;
        o.z = (v[j].z - mean) * rstd * gg.z + bb.z;
        o.w = (v[j].w - mean) * rstd * gg.w + bb.w;
        *reinterpret_cast<float4*>(base + j * 4) = o;
    }
}

// ---------- staging helpers ----------
__device__ __forceinline__ void stage_plain(float* dst, const float* src) {
    // 4096 floats, [E][E] row-major
    float4* d4 = reinterpret_cast<float4*>(dst);
    const float4* s4 = reinterpret_cast<const float4*>(src);
    const int tid = threadIdx.x;
#pragma unroll
    for (int i = 0; i < 8; i++) d4[tid + i * NTHREADS] = s4[tid + i * NTHREADS];
}
__device__ __forceinline__ void stage_qkv(float* dst, const float* src) {
    // rearrange [h][e][k] -> [e][h*16+k], 4096 floats
    float4* d4 = reinterpret_cast<float4*>(dst);
    const int tid = threadIdx.x;
#pragma unroll
    for (int i = 0; i < 8; i++) {
        int idx = tid + i * NTHREADS;
        int e = idx >> 4, cq = idx & 15;
        d4[idx] = *reinterpret_cast<const float4*>(
            src + ((cq >> 2) << 10) + e * 16 + ((cq & 3) << 2));
    }
}

// Shared memory layout (floats)
#define SM_XS   0
#define SM_WS0  (SM_XS + 4096)       // 4096
#define SM_WS1  (SM_WS0 + 4096)      // 8192
#define SM_Q    (SM_WS1 + 4096)      // 12288
#define SM_K    (SM_Q + 4096)        // 16384
#define SM_V    (SM_K + 4096)        // 20480
#define SM_LN   (SM_V + 4096)        // 24576  (256 floats: ln1g ln1b ln2g ln2b)
#define SM_FLOATS (SM_LN + 256)      // 24832
#define SMEM_BYTES (SM_FLOATS * 4)   // 99,328 B

__global__ void __launch_bounds__(NTHREADS, 2)
bert_fused_kernel(const int* __restrict__ data,
                  const float* __restrict__ tok_emb,
                  const float* __restrict__ pos_emb,
                  const float* __restrict__ Wq,
                  const float* __restrict__ Wk,
                  const float* __restrict__ Wv,
                  const float* __restrict__ Wo,
                  const float* __restrict__ bo,
                  const float* __restrict__ ln1g,
                  const float* __restrict__ ln1b,
                  const float* __restrict__ ln2g,
                  const float* __restrict__ ln2b,
                  const float* __restrict__ W1,
                  const float* __restrict__ b1,
                  const float* __restrict__ W2,
                  const float* __restrict__ b2,
                  const float* __restrict__ Wout,
                  const float* __restrict__ bout,
                  float* __restrict__ out) {
    extern __shared__ float sm[];
    float* xs  = sm + SM_XS;
    float* ws0 = sm + SM_WS0;
    float* ws1 = sm + SM_WS1;
    float* qb  = sm + SM_Q;
    float* kb  = sm + SM_K;
    float* vb  = sm + SM_V;
    float* ln  = sm + SM_LN;

    const int tid = threadIdx.x;
    const int blk = blockIdx.x;

    // ---------------- embedding: xs[r][e] = tok_emb[tok][e] + pos_emb[t][e]
    {
        const int e2 = (tid & 31) * 2;
        const int r0 = tid >> 5;             // 0..3
#pragma unroll
        for (int it = 0; it < 16; ++it) {
            int r = it * 4 + r0;
            int b = blk * G + (r >> 4);
            int t = r & 15;
            int tok = data[b * TT + t];
            float2 te = *reinterpret_cast<const float2*>(tok_emb + tok * EE + e2);
            float2 pe = *reinterpret_cast<const float2*>(pos_emb + t * EE + e2);
            *reinterpret_cast<float2*>(xs + r * STR + e2) =
                make_float2(te.x + pe.x, te.y + pe.y);
        }
    }
    __syncthreads();   // S0: xs ready

    for (int l = 0; l < LL; l++) {
        // -------- stage Wq, Wk, LN params
        stage_qkv(ws0, Wq + l * 4096);
        stage_qkv(ws1, Wk + l * 4096);
        ln[tid]       = (tid < 64) ? ln1g[l * 64 + tid] : ln1b[l * 64 + tid - 64];
        ln[128 + tid] = (tid < 64) ? ln2g[l * 64 + tid] : ln2b[l * 64 + tid - 64];
        __syncthreads();   // S1

        // -------- gemm Q, gemm K (disjoint outputs, no sync between)
        gemm64(xs, ws0, [&](int r, int c0, float4 v) {
            *reinterpret_cast<float4*>(qb + r * STR + c0) = v;
        });
        gemm64(xs, ws1, [&](int r, int c0, float4 v) {
            *reinterpret_cast<float4*>(kb + r * STR + c0) = v;
        });
        __syncthreads();   // S2: q,k ready; ws0/ws1 free

        // -------- stage Wv, Wo
        stage_qkv(ws0, Wv + l * 4096);
        stage_plain(ws1, Wo + l * 4096);
        __syncthreads();   // S3

        // -------- gemm V
        gemm64(xs, ws0, [&](int r, int c0, float4 v) {
            *reinterpret_cast<float4*>(vb + r * STR + c0) = v;
        });
        __syncthreads();   // S4: v ready; ws0 free

        // -------- stage W1 (overlaps attention) + attention
        stage_plain(ws0, W1 + l * 4096);
        {
#pragma unroll
            for (int half = 0; half < 2; half++) {
                const int item = tid + half * NTHREADS;
                const int g = item >> 6, h = (item >> 4) & 3, t = item & 15;
                const int r = (g << 4) + t;
                const int ch = h << 4;
                const float4* q4 = reinterpret_cast<const float4*>(qb + r * STR + ch);
                float4 qa = q4[0], qbv = q4[1], qc = q4[2], qd = q4[3];
                const float* kbase = kb + (g << 10) + ch;   // row g*16, col h*16
                const float* vbase = vb + (g << 10) + ch;
                float p[16];
                float mx = -1e30f;
#pragma unroll
                for (int s = 0; s < 16; s++) {
                    const float4* k4 = reinterpret_cast<const float4*>(kbase + (s << 6));
                    float4 ka = k4[0], kb2 = k4[1], kc = k4[2], kd = k4[3];
                    float acc = qa.x * ka.x + qa.y * ka.y + qa.z * ka.z + qa.w * ka.w
                              + qbv.x * kb2.x + qbv.y * kb2.y + qbv.z * kb2.z + qbv.w * kb2.w
                              + qc.x * kc.x + qc.y * kc.y + qc.z * kc.z + qc.w * kc.w
                              + qd.x * kd.x + qd.y * kd.y + qd.z * kd.z + qd.w * kd.w;
                    acc *= 0.25f;
                    p[s] = acc;
                    mx = fmaxf(mx, acc);
                }
                float sum = 0.f;
#pragma unroll
                for (int s = 0; s < 16; s++) { p[s] = __expf(p[s] - mx); sum += p[s]; }
                float inv = 1.f / sum;
                float4 oa = make_float4(0, 0, 0, 0), ob = oa, oc = oa, od = oa;
#pragma unroll
                for (int s = 0; s < 16; s++) {
                    float ps = p[s];
                    const float4* v4 = reinterpret_cast<const float4*>(vbase + (s << 6));
                    float4 va = v4[0], vb2 = v4[1], vc = v4[2], vd = v4[3];
                    oa.x += ps * va.x; oa.y += ps * va.y; oa.z += ps * va.z; oa.w += ps * va.w;
                    ob.x += ps * vb2.x; ob.y += ps * vb2.y; ob.z += ps * vb2.z; ob.w += ps * vb2.w;
                    oc.x += ps * vc.x; oc.y += ps * vc.y; oc.z += ps * vc.z; oc.w += ps * vc.w;
                    od.x += ps * vd.x; od.y += ps * vd.y; od.z += ps * vd.z; od.w += ps * vd.w;
                }
                // write o back into this item's own q slot (exclusive)
                float4* orow = reinterpret_cast<float4*>(qb + r * STR + ch);
                oa.x *= inv; oa.y *= inv; oa.z *= inv; oa.w *= inv;
                ob.x *= inv; ob.y *= inv; ob.z *= inv; ob.w *= inv;
                oc.x *= inv; oc.y *= inv; oc.z *= inv; oc.w *= inv;
                od.x *= inv; od.y *= inv; od.z *= inv; od.w *= inv;
                orow[0] = oa; orow[1] = ob; orow[2] = oc; orow[3] = od;
            }
        }
        __syncthreads();   // S5: o(in qb) ready, W1 staged

        // -------- output projection + residual: xs += o @ Wo + bo
        {
            const float* bop = bo + l * 64;
            gemm64(qb, ws1, [&](int r, int c0, float4 v) {
                float4 bb = *reinterpret_cast<const float4*>(bop + c0);
                float4 x0 = *reinterpret_cast<const float4*>(xs + r * STR + c0);
                v.x += bb.x + x0.x; v.y += bb.y + x0.y;
                v.z += bb.z + x0.z; v.w += bb.w + x0.w;
                *reinterpret_cast<float4*>(xs + r * STR + c0) = v;
            });
        }
        __syncthreads();   // S6: xs updated; ws1 free

        // -------- LN1 + stage W2 (overlap)
        stage_plain(ws1, W2 + l * 4096);
        layer_norm(xs, ln, ln + 64);
        __syncthreads();   // S7

        // -------- FF1: kb = relu(xs @ W1 + b1)
        {
            const float* bp = b1 + l * 64;
            gemm64(xs, ws0, [&](int r, int c0, float4 v) {
                float4 bb = *reinterpret_cast<const float4*>(bp + c0);
                v.x = fmaxf(v.x + bb.x, 0.f); v.y = fmaxf(v.y + bb.y, 0.f);
                v.z = fmaxf(v.z + bb.z, 0.f); v.w = fmaxf(v.w + bb.w, 0.f);
                *reinterpret_cast<float4*>(kb + r * STR + c0) = v;
            });
        }
        __syncthreads();   // S8

        // -------- FF2: xs += kb @ W2 + b2
        {
            const float* bp = b2 + l * 64;
            gemm64(kb, ws1, [&](int r, int c0, float4 v) {
                float4 bb = *reinterpret_cast<const float4*>(bp + c0);
                float4 x0 = *reinterpret_cast<const float4*>(xs + r * STR + c0);
                v.x += bb.x + x0.x; v.y += bb.y + x0.y;
                v.z += bb.z + x0.z; v.w += bb.w + x0.w;
                *reinterpret_cast<float4*>(xs + r * STR + c0) = v;
            });
        }
        __syncthreads();   // S9

        // -------- LN2
        layer_norm(xs, ln + 128, ln + 192);
        __syncthreads();   // S10
    }

    // ---------------- final projection: out = xs @ Wout + bout
    {
        // 6144 floats into ws0..ws1 (contiguous 8192 region)
        float4* d4 = reinterpret_cast<float4*>(ws0);
        const float4* s4 = reinterpret_cast<const float4*>(Wout);
#pragma unroll
        for (int i = 0; i < 12; i++) d4[tid + i * NTHREADS] = s4[tid + i * NTHREADS];
    }
    __syncthreads();
    gemm96(xs, ws0, bout, out + (size_t)blk * ROWS * VOCAB);
}

extern "C" void kernel_launch(void* const* d_in, const int* in_sizes, int n_in,
                              void* d_out, int out_size) {
    const int*   data    = (const int*)d_in[0];
    const float* tok_emb = (const float*)d_in[1];
    const float* pos_emb = (const float*)d_in[2];
    const float* Wq      = (const float*)d_in[3];
    const float* Wk      = (const float*)d_in[4];
    const float* Wv      = (const float*)d_in[5];
    const float* Wo      = (const float*)d_in[6];
    const float* bo      = (const float*)d_in[7];
    const float* ln1g    = (const float*)d_in[8];
    const float* ln1b    = (const float*)d_in[9];
    const float* ln2g    = (const float*)d_in[10];
    const float* ln2b    = (const float*)d_in[11];
    const float* W1      = (const float*)d_in[12];
    const float* b1      = (const float*)d_in[13];
    const float* W2      = (const float*)d_in[14];
    const float* b2      = (const float*)d_in[15];
    const float* Wout    = (const float*)d_in[16];
    const float* bout    = (const float*)d_in[17];
    float* out = (float*)d_out;

    cudaFuncSetAttribute(bert_fused_kernel,
                         cudaFuncAttributeMaxDynamicSharedMemorySize, SMEM_BYTES);
    bert_fused_kernel<<<BB / G, NTHREADS, SMEM_BYTES>>>(
        data, tok_emb, pos_emb, Wq, Wk, Wv, Wo, bo,
        ln1g, ln1b, ln2g, ln2b, W1, b1, W2, b2, Wout, bout, out);
}

// round 8
// speedup vs baseline: 1.8880x; 1.8880x over previous
#include <cuda_runtime.h>
#include <cuda_bf16.h>
#include <cstdint>

#define VOCAB 96
#define TT 16
#define EE 64
#define LL 4
#define BB 16384
#define G 8
#define ROWS 128
#define NT 256

// bf16 row stride: 72 bf16 = 144 bytes (conflict-free for frag access: bank = 4r + j)
#define RS 144

// smem offsets (bytes)
#define O_CST  0
#define O_WTH  2176
#define O_WTL  (O_WTH + 55296)
#define O_XAH  (O_WTL + 55296)
#define O_XAL  (O_XAH + 18432)
#define O_QH   (O_XAL + 18432)
#define O_KH   (O_QH  + 18432)
#define O_VH   (O_KH  + 18432)
#define O_VL   (O_VH  + 18432)
#define SMEM_BYTES (O_VL + 18432)   // 223360

#define SLOT 9216                    // one 64x72 bf16 weight slot
#define LAYER_ELEMS (6*64*72)        // 27648
#define WOUT_OFF (4*LAYER_ELEMS)     // 110592
#define TOTAL_W  (WOUT_OFF + 96*72)  // 117504

__device__ __align__(16) __nv_bfloat16 g_wth[TOTAL_W];
__device__ __align__(16) __nv_bfloat16 g_wtl[TOTAL_W];

// ---------------- helpers ----------------
__device__ __forceinline__ uint32_t phi(float a, float b) {
    __nv_bfloat162 t = __floats2bfloat162_rn(a, b);
    return *reinterpret_cast<uint32_t*>(&t);
}
__device__ __forceinline__ uint32_t plo(float a, float b, uint32_t h) {
    float2 f = __bfloat1622float2(*reinterpret_cast<__nv_bfloat162*>(&h));
    __nv_bfloat162 t = __floats2bfloat162_rn(a - f.x, b - f.y);
    return *reinterpret_cast<uint32_t*>(&t);
}
__device__ __forceinline__ void up2(uint32_t w, float* o) {
    float2 f = __bfloat1622float2(*reinterpret_cast<__nv_bfloat162*>(&w));
    o[0] = f.x; o[1] = f.y;
}
__device__ __forceinline__ void up8(const char* p, float* o) {   // 16B -> 8 floats
    uint4 u = *reinterpret_cast<const uint4*>(p);
    up2(u.x, o); up2(u.y, o + 2); up2(u.z, o + 4); up2(u.w, o + 6);
}
__device__ __forceinline__ void mma16816(float d[4], uint32_t a0, uint32_t a1,
                                         uint32_t a2, uint32_t a3,
                                         uint32_t b0, uint32_t b1) {
    asm volatile(
        "mma.sync.aligned.m16n8k16.row.col.f32.bf16.bf16.f32 "
        "{%0,%1,%2,%3}, {%4,%5,%6,%7}, {%8,%9}, {%0,%1,%2,%3};"
        : "+f"(d[0]), "+f"(d[1]), "+f"(d[2]), "+f"(d[3])
        : "r"(a0), "r"(a1), "r"(a2), "r"(a3), "r"(b0), "r"(b1));
}
// pack activation regs (D-frag layout) into A-frag hi/lo for k-step ks
__device__ __forceinline__ void packA(const float a0[4], const float a1[4],
                                      uint32_t ah[4], uint32_t al[4]) {
    ah[0] = phi(a0[0], a0[1]); al[0] = plo(a0[0], a0[1], ah[0]);
    ah[1] = phi(a0[2], a0[3]); al[1] = plo(a0[2], a0[3], ah[1]);
    ah[2] = phi(a1[0], a1[1]); al[2] = plo(a1[0], a1[1], ah[2]);
    ah[3] = phi(a1[2], a1[3]); al[3] = plo(a1[2], a1[3], ah[3]);
}
// GEMM: acc[NTL][4] += act(16x64, regs) @ W(64 x NTL*8) with 3-term split
template <int NTL>
__device__ __forceinline__ void gemm_reg(const float act[8][4], const char* wh,
                                         const char* wl, float acc[NTL][4],
                                         int r, int j) {
#pragma unroll
    for (int ks = 0; ks < 4; ks++) {
        uint32_t ah[4], al[4];
        packA(act[2 * ks], act[2 * ks + 1], ah, al);
        const char* bh = wh + r * RS + j * 4 + ks * 32;
        const char* bl = wl + r * RS + j * 4 + ks * 32;
#pragma unroll
        for (int nt = 0; nt < NTL; nt++) {
            uint32_t b0 = *reinterpret_cast<const uint32_t*>(bh + nt * 8 * RS);
            uint32_t b1 = *reinterpret_cast<const uint32_t*>(bh + nt * 8 * RS + 16);
            uint32_t c0 = *reinterpret_cast<const uint32_t*>(bl + nt * 8 * RS);
            uint32_t c1 = *reinterpret_cast<const uint32_t*>(bl + nt * 8 * RS + 16);
            mma16816(acc[nt], ah[0], ah[1], ah[2], ah[3], b0, b1);
            mma16816(acc[nt], al[0], al[1], al[2], al[3], b0, b1);
            mma16816(acc[nt], ah[0], ah[1], ah[2], ah[3], c0, c1);
        }
    }
}
// GEMM with A from smem hi/lo (for o @ Wo)
__device__ __forceinline__ void gemm_smem(const char* xah, const char* xal,
                                          const char* wh, const char* wl,
                                          float acc[8][4], int m0, int r, int j) {
#pragma unroll
    for (int ks = 0; ks < 4; ks++) {
        uint32_t off = (m0 + r) * RS + ks * 32 + j * 4;
        uint32_t ah[4], al[4];
        ah[0] = *reinterpret_cast<const uint32_t*>(xah + off);
        ah[1] = *reinterpret_cast<const uint32_t*>(xah + off + 8 * RS);
        ah[2] = *reinterpret_cast<const uint32_t*>(xah + off + 16);
        ah[3] = *reinterpret_cast<const uint32_t*>(xah + off + 8 * RS + 16);
        al[0] = *reinterpret_cast<const uint32_t*>(xal + off);
        al[1] = *reinterpret_cast<const uint32_t*>(xal + off + 8 * RS);
        al[2] = *reinterpret_cast<const uint32_t*>(xal + off + 16);
        al[3] = *reinterpret_cast<const uint32_t*>(xal + off + 8 * RS + 16);
        const char* bh = wh + r * RS + j * 4 + ks * 32;
        const char* bl = wl + r * RS + j * 4 + ks * 32;
#pragma unroll
        for (int nt = 0; nt < 8; nt++) {
            uint32_t b0 = *reinterpret_cast<const uint32_t*>(bh + nt * 8 * RS);
            uint32_t b1 = *reinterpret_cast<const uint32_t*>(bh + nt * 8 * RS + 16);
            uint32_t c0 = *reinterpret_cast<const uint32_t*>(bl + nt * 8 * RS);
            uint32_t c1 = *reinterpret_cast<const uint32_t*>(bl + nt * 8 * RS + 16);
            mma16816(acc[nt], ah[0], ah[1], ah[2], ah[3], b0, b1);
            mma16816(acc[nt], al[0], al[1], al[2], al[3], b0, b1);
            mma16816(acc[nt], ah[0], ah[1], ah[2], ah[3], c0, c1);
        }
    }
}
// store fragment rows to bf16 row buffer (hi only)
__device__ __forceinline__ void fstore_hi(char* B, int m0, int r, int j,
                                          const float a[8][4]) {
#pragma unroll
    for (int nt = 0; nt < 8; nt++) {
        uint32_t co = (uint32_t)(nt * 16 + j * 4);
        *reinterpret_cast<uint32_t*>(B + (m0 + r) * RS + co) = phi(a[nt][0], a[nt][1]);
        *reinterpret_cast<uint32_t*>(B + (m0 + r + 8) * RS + co) = phi(a[nt][2], a[nt][3]);
    }
}
__device__ __forceinline__ void fstore_hl(char* BH, char* BL, int m0, int r, int j,
                                          const float a[8][4]) {
#pragma unroll
    for (int nt = 0; nt < 8; nt++) {
        uint32_t co = (uint32_t)(nt * 16 + j * 4);
        uint32_t h0 = phi(a[nt][0], a[nt][1]);
        uint32_t h1 = phi(a[nt][2], a[nt][3]);
        *reinterpret_cast<uint32_t*>(BH + (m0 + r) * RS + co) = h0;
        *reinterpret_cast<uint32_t*>(BH + (m0 + r + 8) * RS + co) = h1;
        *reinterpret_cast<uint32_t*>(BL + (m0 + r) * RS + co) = plo(a[nt][0], a[nt][1], h0);
        *reinterpret_cast<uint32_t*>(BL + (m0 + r + 8) * RS + co) = plo(a[nt][2], a[nt][3], h1);
    }
}
// LayerNorm in fragment layout (rows m and m+8 per thread)
__device__ __forceinline__ void ln_frag(float x[8][4], const float* g, const float* b, int j) {
    float s0 = 0.f, q0 = 0.f, s1 = 0.f, q1 = 0.f;
#pragma unroll
    for (int nt = 0; nt < 8; nt++) {
        s0 += x[nt][0] + x[nt][1]; q0 += x[nt][0] * x[nt][0] + x[nt][1] * x[nt][1];
        s1 += x[nt][2] + x[nt][3]; q1 += x[nt][2] * x[nt][2] + x[nt][3] * x[nt][3];
    }
    s0 += __shfl_xor_sync(0xffffffffu, s0, 1); q0 += __shfl_xor_sync(0xffffffffu, q0, 1);
    s1 += __shfl_xor_sync(0xffffffffu, s1, 1); q1 += __shfl_xor_sync(0xffffffffu, q1, 1);
    s0 += __shfl_xor_sync(0xffffffffu, s0, 2); q0 += __shfl_xor_sync(0xffffffffu, q0, 2);
    s1 += __shfl_xor_sync(0xffffffffu, s1, 2); q1 += __shfl_xor_sync(0xffffffffu, q1, 2);
    float m0 = s0 * (1.f / 64.f), m1 = s1 * (1.f / 64.f);
    float r0 = rsqrtf(q0 * (1.f / 64.f) - m0 * m0 + 1e-5f);
    float r1 = rsqrtf(q1 * (1.f / 64.f) - m1 * m1 + 1e-5f);
#pragma unroll
    for (int nt = 0; nt < 8; nt++) {
        int c = nt * 8 + j * 2;
        float2 gg = *reinterpret_cast<const float2*>(g + c);
        float2 bb = *reinterpret_cast<const float2*>(b + c);
        x[nt][0] = (x[nt][0] - m0) * r0 * gg.x + bb.x;
        x[nt][1] = (x[nt][1] - m0) * r0 * gg.y + bb.y;
        x[nt][2] = (x[nt][2] - m1) * r1 * gg.x + bb.x;
        x[nt][3] = (x[nt][3] - m1) * r1 * gg.y + bb.y;
    }
}

// ---------------- prep kernel: split+transpose all weights to bf16 hi/lo ----------------
__global__ void prep_kernel(const float* __restrict__ Wq, const float* __restrict__ Wk,
                            const float* __restrict__ Wv, const float* __restrict__ Wo,
                            const float* __restrict__ W1, const float* __restrict__ W2,
                            const float* __restrict__ Wout) {
    int gid = blockIdx.x * 256 + threadIdx.x;
    if (gid >= TOTAL_W) return;
    float v = 0.f;
    if (gid < WOUT_OFF) {
        int l = gid / LAYER_ELEMS, r0 = gid % LAYER_ELEMS;
        int slot = r0 / (64 * 72), r1 = r0 % (64 * 72);
        int c = r1 / 72, k = r1 % 72;
        if (k < 64) {
            switch (slot) {
                case 0: v = Wq[l * 4096 + (c >> 4) * 1024 + k * 16 + (c & 15)]; break;
                case 1: v = Wk[l * 4096 + (c >> 4) * 1024 + k * 16 + (c & 15)]; break;
                case 2: v = Wv[l * 4096 + (c >> 4) * 1024 + k * 16 + (c & 15)]; break;
                case 3: v = Wo[l * 4096 + k * 64 + c]; break;
                case 4: v = W1[l * 4096 + k * 64 + c]; break;
                default: v = W2[l * 4096 + k * 64 + c]; break;
            }
        }
    } else {
        int r = gid - WOUT_OFF;
        int c = r / 72, k = r % 72;
        if (k < 64) v = Wout[k * 96 + c];
    }
    __nv_bfloat16 hi = __float2bfloat16(v);
    __nv_bfloat16 lo = __float2bfloat16(v - __bfloat162float(hi));
    g_wth[gid] = hi;
    g_wtl[gid] = lo;
}

// ---------------- main kernel ----------------
__global__ void __launch_bounds__(NT, 1)
bert_mma_kernel(const int* __restrict__ data, const float* __restrict__ tok_emb,
                const float* __restrict__ pos_emb,
                const float* __restrict__ bo,
                const float* __restrict__ ln1g, const float* __restrict__ ln1b,
                const float* __restrict__ ln2g, const float* __restrict__ ln2b,
                const float* __restrict__ b1, const float* __restrict__ b2,
                const float* __restrict__ bout, float* __restrict__ out) {
    extern __shared__ char sm[];
    float* cst = reinterpret_cast<float*>(sm + O_CST);
    char* WTH = sm + O_WTH; char* WTL = sm + O_WTL;
    char* XAH = sm + O_XAH; char* XAL = sm + O_XAL;
    char* QH = sm + O_QH;  char* KH = sm + O_KH;
    char* VH = sm + O_VH;  char* VL = sm + O_VL;

    const int tid = threadIdx.x;
    const int w = tid >> 5, lane = tid & 31;
    const int r = lane >> 2, j = lane & 3;
    const int m0 = w * 16;
    const int blk = blockIdx.x;

    // -------- embedding into x (fragment layout): rows m0+r, m0+r+8 (seq w, t=r / r+8)
    float x[8][4];
    {
        int b = blk * G + w;
        int tokA = data[b * TT + r], tokB = data[b * TT + r + 8];
#pragma unroll
        for (int nt = 0; nt < 8; nt++) {
            int c = nt * 8 + j * 2;
            float2 tA = *reinterpret_cast<const float2*>(tok_emb + tokA * EE + c);
            float2 tB = *reinterpret_cast<const float2*>(tok_emb + tokB * EE + c);
            float2 pA = *reinterpret_cast<const float2*>(pos_emb + r * EE + c);
            float2 pB = *reinterpret_cast<const float2*>(pos_emb + (r + 8) * EE + c);
            x[nt][0] = tA.x + pA.x; x[nt][1] = tA.y + pA.y;
            x[nt][2] = tB.x + pB.x; x[nt][3] = tB.y + pB.y;
        }
    }

    for (int l = 0; l < LL; l++) {
        __syncthreads();   // prior layer's slot reads complete
        // -------- stage all 6 weight slots (pure memcpy) + per-layer consts
        {
            const uint4* sH = reinterpret_cast<const uint4*>(g_wth + l * LAYER_ELEMS);
            const uint4* sL = reinterpret_cast<const uint4*>(g_wtl + l * LAYER_ELEMS);
            uint4* dH = reinterpret_cast<uint4*>(WTH);
            uint4* dL = reinterpret_cast<uint4*>(WTL);
            for (int i = tid; i < 3456; i += NT) { dH[i] = sH[i]; dL[i] = sL[i]; }
            if (tid < 64) {
                cst[tid] = bo[l * 64 + tid];        cst[64 + tid] = b1[l * 64 + tid];
                cst[128 + tid] = b2[l * 64 + tid];  cst[192 + tid] = ln1g[l * 64 + tid];
                cst[256 + tid] = ln1b[l * 64 + tid]; cst[320 + tid] = ln2g[l * 64 + tid];
                cst[384 + tid] = ln2b[l * 64 + tid];
            }
        }
        __syncthreads();

        // -------- Q, K, V gemms (A = x in regs), outputs to smem rows
        {
            float acc[8][4];
#pragma unroll
            for (int nt = 0; nt < 8; nt++) { acc[nt][0] = acc[nt][1] = acc[nt][2] = acc[nt][3] = 0.f; }
            gemm_reg<8>(x, WTH + 0 * SLOT, WTL + 0 * SLOT, acc, r, j);
            fstore_hi(QH, m0, r, j, acc);
#pragma unroll
            for (int nt = 0; nt < 8; nt++) { acc[nt][0] = acc[nt][1] = acc[nt][2] = acc[nt][3] = 0.f; }
            gemm_reg<8>(x, WTH + 1 * SLOT, WTL + 1 * SLOT, acc, r, j);
            fstore_hi(KH, m0, r, j, acc);
#pragma unroll
            for (int nt = 0; nt < 8; nt++) { acc[nt][0] = acc[nt][1] = acc[nt][2] = acc[nt][3] = 0.f; }
            gemm_reg<8>(x, WTH + 2 * SLOT, WTL + 2 * SLOT, acc, r, j);
            fstore_hl(VH, VL, m0, r, j, acc);
        }
        __syncwarp();

        // -------- attention (seq w handled inside warp w): 2 items per lane
#pragma unroll
        for (int it = 0; it < 2; it++) {
            int h = ((lane >> 4) << 1) | it;
            int t = lane & 15;
            int row = m0 + t;
            float q[16];
            up8(QH + row * RS + h * 32, q);
            up8(QH + row * RS + h * 32 + 16, q + 8);
            float p[16], mx = -1e30f;
#pragma unroll
            for (int s = 0; s < 16; s++) {
                float kk[16];
                up8(KH + (m0 + s) * RS + h * 32, kk);
                up8(KH + (m0 + s) * RS + h * 32 + 16, kk + 8);
                float a = 0.f;
#pragma unroll
                for (int i = 0; i < 16; i++) a += q[i] * kk[i];
                a *= 0.25f;
                p[s] = a; mx = fmaxf(mx, a);
            }
            float sum = 0.f;
#pragma unroll
            for (int s = 0; s < 16; s++) { p[s] = __expf(p[s] - mx); sum += p[s]; }
            float inv = 1.f / sum;
            float o[16];
#pragma unroll
            for (int i = 0; i < 16; i++) o[i] = 0.f;
#pragma unroll
            for (int s = 0; s < 16; s++) {
                float vh[16], vl2[16];
                up8(VH + (m0 + s) * RS + h * 32, vh);
                up8(VH + (m0 + s) * RS + h * 32 + 16, vh + 8);
                up8(VL + (m0 + s) * RS + h * 32, vl2);
                up8(VL + (m0 + s) * RS + h * 32 + 16, vl2 + 8);
                float ps = p[s];
#pragma unroll
                for (int i = 0; i < 16; i++) o[i] += ps * (vh[i] + vl2[i]);
            }
            // store o (scaled) to XA hi/lo at row, cols h*16..+15
            uint32_t hw[8], lw[8];
#pragma unroll
            for (int pz = 0; pz < 8; pz++) {
                float a = o[2 * pz] * inv, b = o[2 * pz + 1] * inv;
                hw[pz] = phi(a, b);
                lw[pz] = plo(a, b, hw[pz]);
            }
            char* dh = XAH + row * RS + h * 32;
            char* dl = XAL + row * RS + h * 32;
            *reinterpret_cast<uint4*>(dh) = make_uint4(hw[0], hw[1], hw[2], hw[3]);
            *reinterpret_cast<uint4*>(dh + 16) = make_uint4(hw[4], hw[5], hw[6], hw[7]);
            *reinterpret_cast<uint4*>(dl) = make_uint4(lw[0], lw[1], lw[2], lw[3]);
            *reinterpret_cast<uint4*>(dl + 16) = make_uint4(lw[4], lw[5], lw[6], lw[7]);
        }
        __syncwarp();

        // -------- o @ Wo + bo + x ; LN1
        {
            float acc[8][4];
#pragma unroll
            for (int nt = 0; nt < 8; nt++) { acc[nt][0] = acc[nt][1] = acc[nt][2] = acc[nt][3] = 0.f; }
            gemm_smem(XAH, XAL, WTH + 3 * SLOT, WTL + 3 * SLOT, acc, m0, r, j);
#pragma unroll
            for (int nt = 0; nt < 8; nt++) {
                int c = nt * 8 + j * 2;
                float2 bb = *reinterpret_cast<const float2*>(cst + c);
                x[nt][0] += acc[nt][0] + bb.x; x[nt][1] += acc[nt][1] + bb.y;
                x[nt][2] += acc[nt][2] + bb.x; x[nt][3] += acc[nt][3] + bb.y;
            }
            ln_frag(x, cst + 192, cst + 256, j);
        }

        // -------- FF1 (regs) -> relu -> FF2 (regs) -> residual -> LN2
        {
            float t1[8][4];
#pragma unroll
            for (int nt = 0; nt < 8; nt++) { t1[nt][0] = t1[nt][1] = t1[nt][2] = t1[nt][3] = 0.f; }
            gemm_reg<8>(x, WTH + 4 * SLOT, WTL + 4 * SLOT, t1, r, j);
#pragma unroll
            for (int nt = 0; nt < 8; nt++) {
                int c = nt * 8 + j * 2;
                float2 bb = *reinterpret_cast<const float2*>(cst + 64 + c);
                t1[nt][0] = fmaxf(t1[nt][0] + bb.x, 0.f); t1[nt][1] = fmaxf(t1[nt][1] + bb.y, 0.f);
                t1[nt][2] = fmaxf(t1[nt][2] + bb.x, 0.f); t1[nt][3] = fmaxf(t1[nt][3] + bb.y, 0.f);
            }
            float acc[8][4];
#pragma unroll
            for (int nt = 0; nt < 8; nt++) { acc[nt][0] = acc[nt][1] = acc[nt][2] = acc[nt][3] = 0.f; }
            gemm_reg<8>(t1, WTH + 5 * SLOT, WTL + 5 * SLOT, acc, r, j);
#pragma unroll
            for (int nt = 0; nt < 8; nt++) {
                int c = nt * 8 + j * 2;
                float2 bb = *reinterpret_cast<const float2*>(cst + 128 + c);
                x[nt][0] += acc[nt][0] + bb.x; x[nt][1] += acc[nt][1] + bb.y;
                x[nt][2] += acc[nt][2] + bb.x; x[nt][3] += acc[nt][3] + bb.y;
            }
            ln_frag(x, cst + 320, cst + 384, j);
        }
    }

    // -------- final projection: out = x @ Wout + bout (N=96 -> 12 n-tiles)
    __syncthreads();
    {
        const uint4* sH = reinterpret_cast<const uint4*>(g_wth + WOUT_OFF);
        const uint4* sL = reinterpret_cast<const uint4*>(g_wtl + WOUT_OFF);
        uint4* dH = reinterpret_cast<uint4*>(WTH);
        uint4* dL = reinterpret_cast<uint4*>(WTL);
        for (int i = tid; i < 864; i += NT) { dH[i] = sH[i]; dL[i] = sL[i]; }
        if (tid < 96) cst[tid] = bout[tid];
    }
    __syncthreads();
    {
        float acc[12][4];
#pragma unroll
        for (int nt = 0; nt < 12; nt++) { acc[nt][0] = acc[nt][1] = acc[nt][2] = acc[nt][3] = 0.f; }
        gemm_reg<12>(x, WTH, WTL, acc, r, j);
        float* o0 = out + (size_t)(blk * ROWS + m0 + r) * VOCAB;
        float* o1 = out + (size_t)(blk * ROWS + m0 + r + 8) * VOCAB;
#pragma unroll
        for (int nt = 0; nt < 12; nt++) {
            int c = nt * 8 + j * 2;
            float2 bb = *reinterpret_cast<const float2*>(cst + c);
            *reinterpret_cast<float2*>(o0 + c) = make_float2(acc[nt][0] + bb.x, acc[nt][1] + bb.y);
            *reinterpret_cast<float2*>(o1 + c) = make_float2(acc[nt][2] + bb.x, acc[nt][3] + bb.y);
        }
    }
}

extern "C" void kernel_launch(void* const* d_in, const int* in_sizes, int n_in,
                              void* d_out, int out_size) {
    const int*   data    = (const int*)d_in[0];
    const float* tok_emb = (const float*)d_in[1];
    const float* pos_emb = (const float*)d_in[2];
    const float* Wq      = (const float*)d_in[3];
    const float* Wk      = (const float*)d_in[4];
    const float* Wv      = (const float*)d_in[5];
    const float* Wo      = (const float*)d_in[6];
    const float* bo      = (const float*)d_in[7];
    const float* ln1g    = (const float*)d_in[8];
    const float* ln1b    = (const float*)d_in[9];
    const float* ln2g    = (const float*)d_in[10];
    const float* ln2b    = (const float*)d_in[11];
    const float* W1      = (const float*)d_in[12];
    const float* b1      = (const float*)d_in[13];
    const float* W2      = (const float*)d_in[14];
    const float* b2      = (const float*)d_in[15];
    const float* Wout    = (const float*)d_in[16];
    const float* bout    = (const float*)d_in[17];
    float* out = (float*)d_out;

    prep_kernel<<<(TOTAL_W + 255) / 256, 256>>>(Wq, Wk, Wv, Wo, W1, W2, Wout);
    cudaFuncSetAttribute(bert_mma_kernel,
                         cudaFuncAttributeMaxDynamicSharedMemorySize, SMEM_BYTES);
    bert_mma_kernel<<<BB / G, NT, SMEM_BYTES>>>(
        data, tok_emb, pos_emb, bo, ln1g, ln1b, ln2g, ln2b,
        b1, b2, bout, out);
}

// round 9
// speedup vs baseline: 2.2502x; 1.1919x over previous
#include <cuda_runtime.h>
#include <cuda_bf16.h>
#include <cstdint>

#define VOCAB 96
#define TT 16
#define EE 64
#define LL 4
#define BB 16384
#define G 4
#define ROWS 64
#define NT 128

#define RS 144           // bf16 row stride bytes (72 bf16)
#define VSTR 68          // fp32 V row stride (floats)

// smem offsets (bytes)
#define O_CST  0
#define O_WTH  2048
#define O_WTL  (O_WTH + 27648)
#define O_XAH  (O_WTL + 27648)
#define O_XAL  (O_XAH + 9216)
#define O_QH   (O_XAL + 9216)
#define O_KH   (O_QH  + 9216)
#define O_VF   (O_KH  + 9216)
#define SMEM_BYTES (O_VF + ROWS * VSTR * 4)   // 111616

#define SLOT 9216                     // one 64x72 bf16 weight slot (bytes)
#define SLOT_ELEMS (64*72)
#define LAYER_ELEMS (6*SLOT_ELEMS)    // 27648
#define WOUT_OFF (4*LAYER_ELEMS)
#define TOTAL_W  (WOUT_OFF + 96*72)

__device__ __align__(16) __nv_bfloat16 g_wth[TOTAL_W];
__device__ __align__(16) __nv_bfloat16 g_wtl[TOTAL_W];

// ---------------- helpers ----------------
__device__ __forceinline__ uint32_t phi(float a, float b) {
    __nv_bfloat162 t = __floats2bfloat162_rn(a, b);
    return *reinterpret_cast<uint32_t*>(&t);
}
__device__ __forceinline__ uint32_t plo(float a, float b, uint32_t h) {
    float2 f = __bfloat1622float2(*reinterpret_cast<__nv_bfloat162*>(&h));
    __nv_bfloat162 t = __floats2bfloat162_rn(a - f.x, b - f.y);
    return *reinterpret_cast<uint32_t*>(&t);
}
__device__ __forceinline__ void up2(uint32_t w, float* o) {
    float2 f = __bfloat1622float2(*reinterpret_cast<__nv_bfloat162*>(&w));
    o[0] = f.x; o[1] = f.y;
}
__device__ __forceinline__ void up8(const char* p, float* o) {
    uint4 u = *reinterpret_cast<const uint4*>(p);
    up2(u.x, o); up2(u.y, o + 2); up2(u.z, o + 4); up2(u.w, o + 6);
}
__device__ __forceinline__ void mma16816(float d[4], uint32_t a0, uint32_t a1,
                                         uint32_t a2, uint32_t a3,
                                         uint32_t b0, uint32_t b1) {
    asm volatile(
        "mma.sync.aligned.m16n8k16.row.col.f32.bf16.bf16.f32 "
        "{%0,%1,%2,%3}, {%4,%5,%6,%7}, {%8,%9}, {%0,%1,%2,%3};"
        : "+f"(d[0]), "+f"(d[1]), "+f"(d[2]), "+f"(d[3])
        : "r"(a0), "r"(a1), "r"(a2), "r"(a3), "r"(b0), "r"(b1));
}
__device__ __forceinline__ void packA(const float a0[4], const float a1[4],
                                      uint32_t ah[4], uint32_t al[4]) {
    ah[0] = phi(a0[0], a0[1]); al[0] = plo(a0[0], a0[1], ah[0]);
    ah[1] = phi(a0[2], a0[3]); al[1] = plo(a0[2], a0[3], ah[1]);
    ah[2] = phi(a1[0], a1[1]); al[2] = plo(a1[0], a1[1], ah[2]);
    ah[3] = phi(a1[2], a1[3]); al[3] = plo(a1[2], a1[3], ah[3]);
}
template <int NTL>
__device__ __forceinline__ void gemm_reg(const float act[8][4], const char* wh,
                                         const char* wl, float acc[NTL][4],
                                         int r, int j) {
#pragma unroll
    for (int ks = 0; ks < 4; ks++) {
        uint32_t ah[4], al[4];
        packA(act[2 * ks], act[2 * ks + 1], ah, al);
        const char* bh = wh + r * RS + j * 4 + ks * 32;
        const char* bl = wl + r * RS + j * 4 + ks * 32;
#pragma unroll
        for (int nt = 0; nt < NTL; nt++) {
            uint32_t b0 = *reinterpret_cast<const uint32_t*>(bh + nt * 8 * RS);
            uint32_t b1 = *reinterpret_cast<const uint32_t*>(bh + nt * 8 * RS + 16);
            uint32_t c0 = *reinterpret_cast<const uint32_t*>(bl + nt * 8 * RS);
            uint32_t c1 = *reinterpret_cast<const uint32_t*>(bl + nt * 8 * RS + 16);
            mma16816(acc[nt], ah[0], ah[1], ah[2], ah[3], b0, b1);
            mma16816(acc[nt], al[0], al[1], al[2], al[3], b0, b1);
            mma16816(acc[nt], ah[0], ah[1], ah[2], ah[3], c0, c1);
        }
    }
}
__device__ __forceinline__ void gemm_smem(const char* xah, const char* xal,
                                          const char* wh, const char* wl,
                                          float acc[8][4], int m0, int r, int j) {
#pragma unroll
    for (int ks = 0; ks < 4; ks++) {
        uint32_t off = (m0 + r) * RS + ks * 32 + j * 4;
        uint32_t ah[4], al[4];
        ah[0] = *reinterpret_cast<const uint32_t*>(xah + off);
        ah[1] = *reinterpret_cast<const uint32_t*>(xah + off + 8 * RS);
        ah[2] = *reinterpret_cast<const uint32_t*>(xah + off + 16);
        ah[3] = *reinterpret_cast<const uint32_t*>(xah + off + 8 * RS + 16);
        al[0] = *reinterpret_cast<const uint32_t*>(xal + off);
        al[1] = *reinterpret_cast<const uint32_t*>(xal + off + 8 * RS);
        al[2] = *reinterpret_cast<const uint32_t*>(xal + off + 16);
        al[3] = *reinterpret_cast<const uint32_t*>(xal + off + 8 * RS + 16);
        const char* bh = wh + r * RS + j * 4 + ks * 32;
        const char* bl = wl + r * RS + j * 4 + ks * 32;
#pragma unroll
        for (int nt = 0; nt < 8; nt++) {
            uint32_t b0 = *reinterpret_cast<const uint32_t*>(bh + nt * 8 * RS);
            uint32_t b1 = *reinterpret_cast<const uint32_t*>(bh + nt * 8 * RS + 16);
            uint32_t c0 = *reinterpret_cast<const uint32_t*>(bl + nt * 8 * RS);
            uint32_t c1 = *reinterpret_cast<const uint32_t*>(bl + nt * 8 * RS + 16);
            mma16816(acc[nt], ah[0], ah[1], ah[2], ah[3], b0, b1);
            mma16816(acc[nt], al[0], al[1], al[2], al[3], b0, b1);
            mma16816(acc[nt], ah[0], ah[1], ah[2], ah[3], c0, c1);
        }
    }
}
__device__ __forceinline__ void fstore_hi(char* B, int m0, int r, int j,
                                          const float a[8][4]) {
#pragma unroll
    for (int nt = 0; nt < 8; nt++) {
        uint32_t co = (uint32_t)(nt * 16 + j * 4);
        *reinterpret_cast<uint32_t*>(B + (m0 + r) * RS + co) = phi(a[nt][0], a[nt][1]);
        *reinterpret_cast<uint32_t*>(B + (m0 + r + 8) * RS + co) = phi(a[nt][2], a[nt][3]);
    }
}
__device__ __forceinline__ void fstore_f32(float* V, int m0, int r, int j,
                                           const float a[8][4]) {
#pragma unroll
    for (int nt = 0; nt < 8; nt++) {
        int c = nt * 8 + j * 2;
        *reinterpret_cast<float2*>(V + (m0 + r) * VSTR + c) = make_float2(a[nt][0], a[nt][1]);
        *reinterpret_cast<float2*>(V + (m0 + r + 8) * VSTR + c) = make_float2(a[nt][2], a[nt][3]);
    }
}
__device__ __forceinline__ void ln_frag(float x[8][4], const float* g, const float* b, int j) {
    float s0 = 0.f, q0 = 0.f, s1 = 0.f, q1 = 0.f;
#pragma unroll
    for (int nt = 0; nt < 8; nt++) {
        s0 += x[nt][0] + x[nt][1]; q0 += x[nt][0] * x[nt][0] + x[nt][1] * x[nt][1];
        s1 += x[nt][2] + x[nt][3]; q1 += x[nt][2] * x[nt][2] + x[nt][3] * x[nt][3];
    }
    s0 += __shfl_xor_sync(0xffffffffu, s0, 1); q0 += __shfl_xor_sync(0xffffffffu, q0, 1);
    s1 += __shfl_xor_sync(0xffffffffu, s1, 1); q1 += __shfl_xor_sync(0xffffffffu, q1, 1);
    s0 += __shfl_xor_sync(0xffffffffu, s0, 2); q0 += __shfl_xor_sync(0xffffffffu, q0, 2);
    s1 += __shfl_xor_sync(0xffffffffu, s1, 2); q1 += __shfl_xor_sync(0xffffffffu, q1, 2);
    float m0 = s0 * (1.f / 64.f), m1 = s1 * (1.f / 64.f);
    float r0 = rsqrtf(q0 * (1.f / 64.f) - m0 * m0 + 1e-5f);
    float r1 = rsqrtf(q1 * (1.f / 64.f) - m1 * m1 + 1e-5f);
#pragma unroll
    for (int nt = 0; nt < 8; nt++) {
        int c = nt * 8 + j * 2;
        float2 gg = *reinterpret_cast<const float2*>(g + c);
        float2 bb = *reinterpret_cast<const float2*>(b + c);
        x[nt][0] = (x[nt][0] - m0) * r0 * gg.x + bb.x;
        x[nt][1] = (x[nt][1] - m0) * r0 * gg.y + bb.y;
        x[nt][2] = (x[nt][2] - m1) * r1 * gg.x + bb.x;
        x[nt][3] = (x[nt][3] - m1) * r1 * gg.y + bb.y;
    }
}

// ---------------- prep kernel ----------------
__global__ void prep_kernel(const float* __restrict__ Wq, const float* __restrict__ Wk,
                            const float* __restrict__ Wv, const float* __restrict__ Wo,
                            const float* __restrict__ W1, const float* __restrict__ W2,
                            const float* __restrict__ Wout) {
    int gid = blockIdx.x * 256 + threadIdx.x;
    if (gid >= TOTAL_W) return;
    float v = 0.f;
    if (gid < WOUT_OFF) {
        int l = gid / LAYER_ELEMS, r0 = gid % LAYER_ELEMS;
        int slot = r0 / SLOT_ELEMS, r1 = r0 % SLOT_ELEMS;
        int c = r1 / 72, k = r1 % 72;
        if (k < 64) {
            switch (slot) {
                case 0: v = Wq[l * 4096 + (c >> 4) * 1024 + k * 16 + (c & 15)]; break;
                case 1: v = Wk[l * 4096 + (c >> 4) * 1024 + k * 16 + (c & 15)]; break;
                case 2: v = Wv[l * 4096 + (c >> 4) * 1024 + k * 16 + (c & 15)]; break;
                case 3: v = Wo[l * 4096 + k * 64 + c]; break;
                case 4: v = W1[l * 4096 + k * 64 + c]; break;
                default: v = W2[l * 4096 + k * 64 + c]; break;
            }
        }
    } else {
        int r = gid - WOUT_OFF;
        int c = r / 72, k = r % 72;
        if (k < 64) v = Wout[k * 96 + c];
    }
    __nv_bfloat16 hi = __float2bfloat16(v);
    __nv_bfloat16 lo = __float2bfloat16(v - __bfloat162float(hi));
    g_wth[gid] = hi;
    g_wtl[gid] = lo;
}

// ---------------- main kernel ----------------
__global__ void __launch_bounds__(NT, 2)
bert_mma_kernel(const int* __restrict__ data, const float* __restrict__ tok_emb,
                const float* __restrict__ pos_emb,
                const float* __restrict__ bo,
                const float* __restrict__ ln1g, const float* __restrict__ ln1b,
                const float* __restrict__ ln2g, const float* __restrict__ ln2b,
                const float* __restrict__ b1, const float* __restrict__ b2,
                const float* __restrict__ bout, float* __restrict__ out) {
    extern __shared__ char sm[];
    float* cst = reinterpret_cast<float*>(sm + O_CST);
    char* WTH = sm + O_WTH; char* WTL = sm + O_WTL;
    char* XAH = sm + O_XAH; char* XAL = sm + O_XAL;
    char* QH = sm + O_QH;  char* KH = sm + O_KH;
    float* VF = reinterpret_cast<float*>(sm + O_VF);

    const int tid = threadIdx.x;
    const int w = tid >> 5, lane = tid & 31;
    const int r = lane >> 2, j = lane & 3;
    const int m0 = w * 16;
    const int blk = blockIdx.x;

    // -------- embedding (fragment layout)
    float x[8][4];
    {
        int b = blk * G + w;
        int tokA = data[b * TT + r], tokB = data[b * TT + r + 8];
#pragma unroll
        for (int nt = 0; nt < 8; nt++) {
            int c = nt * 8 + j * 2;
            float2 tA = *reinterpret_cast<const float2*>(tok_emb + tokA * EE + c);
            float2 tB = *reinterpret_cast<const float2*>(tok_emb + tokB * EE + c);
            float2 pA = *reinterpret_cast<const float2*>(pos_emb + r * EE + c);
            float2 pB = *reinterpret_cast<const float2*>(pos_emb + (r + 8) * EE + c);
            x[nt][0] = tA.x + pA.x; x[nt][1] = tA.y + pA.y;
            x[nt][2] = tB.x + pB.x; x[nt][3] = tB.y + pB.y;
        }
    }

    for (int l = 0; l < LL; l++) {
        __syncthreads();   // previous layer's weight-slot reads complete
        // -------- phase A: stage Q,K,V slots + consts
        {
            const uint4* sH = reinterpret_cast<const uint4*>(g_wth + l * LAYER_ELEMS);
            const uint4* sL = reinterpret_cast<const uint4*>(g_wtl + l * LAYER_ELEMS);
            uint4* dH = reinterpret_cast<uint4*>(WTH);
            uint4* dL = reinterpret_cast<uint4*>(WTL);
            for (int i = tid; i < 1728; i += NT) { dH[i] = sH[i]; dL[i] = sL[i]; }
            if (tid < 64) {
                cst[tid] = bo[l * 64 + tid];         cst[64 + tid] = b1[l * 64 + tid];
                cst[128 + tid] = b2[l * 64 + tid];   cst[192 + tid] = ln1g[l * 64 + tid];
                cst[256 + tid] = ln1b[l * 64 + tid]; cst[320 + tid] = ln2g[l * 64 + tid];
                cst[384 + tid] = ln2b[l * 64 + tid];
            }
        }
        __syncthreads();

        // -------- Q, K, V gemms
        {
            float acc[8][4];
#pragma unroll
            for (int nt = 0; nt < 8; nt++) { acc[nt][0] = acc[nt][1] = acc[nt][2] = acc[nt][3] = 0.f; }
            gemm_reg<8>(x, WTH + 0 * SLOT, WTL + 0 * SLOT, acc, r, j);
            fstore_hi(QH, m0, r, j, acc);
#pragma unroll
            for (int nt = 0; nt < 8; nt++) { acc[nt][0] = acc[nt][1] = acc[nt][2] = acc[nt][3] = 0.f; }
            gemm_reg<8>(x, WTH + 1 * SLOT, WTL + 1 * SLOT, acc, r, j);
            fstore_hi(KH, m0, r, j, acc);
#pragma unroll
            for (int nt = 0; nt < 8; nt++) { acc[nt][0] = acc[nt][1] = acc[nt][2] = acc[nt][3] = 0.f; }
            gemm_reg<8>(x, WTH + 2 * SLOT, WTL + 2 * SLOT, acc, r, j);
            fstore_f32(VF, m0, r, j, acc);
        }
        __syncwarp();

        // -------- attention (warp-private; V in fp32)
#pragma unroll
        for (int it = 0; it < 2; it++) {
            int h = ((lane >> 4) << 1) | it;
            int t = lane & 15;
            int row = m0 + t;
            float q[16];
            up8(QH + row * RS + h * 32, q);
            up8(QH + row * RS + h * 32 + 16, q + 8);
            float p[16], mx = -1e30f;
#pragma unroll
            for (int s = 0; s < 16; s++) {
                float kk[16];
                up8(KH + (m0 + s) * RS + h * 32, kk);
                up8(KH + (m0 + s) * RS + h * 32 + 16, kk + 8);
                float a = 0.f;
#pragma unroll
                for (int i = 0; i < 16; i++) a += q[i] * kk[i];
                a *= 0.25f;
                p[s] = a; mx = fmaxf(mx, a);
            }
            float sum = 0.f;
#pragma unroll
            for (int s = 0; s < 16; s++) { p[s] = __expf(p[s] - mx); sum += p[s]; }
            float inv = 1.f / sum;
            float o[16];
#pragma unroll
            for (int i = 0; i < 16; i++) o[i] = 0.f;
#pragma unroll
            for (int s = 0; s < 16; s++) {
                const float4* v4 = reinterpret_cast<const float4*>(VF + (m0 + s) * VSTR + h * 16);
                float4 a0 = v4[0], a1 = v4[1], a2 = v4[2], a3 = v4[3];
                float ps = p[s];
                o[0] += ps * a0.x; o[1] += ps * a0.y; o[2] += ps * a0.z; o[3] += ps * a0.w;
                o[4] += ps * a1.x; o[5] += ps * a1.y; o[6] += ps * a1.z; o[7] += ps * a1.w;
                o[8] += ps * a2.x; o[9] += ps * a2.y; o[10] += ps * a2.z; o[11] += ps * a2.w;
                o[12] += ps * a3.x; o[13] += ps * a3.y; o[14] += ps * a3.z; o[15] += ps * a3.w;
            }
            uint32_t hw[8], lw[8];
#pragma unroll
            for (int pz = 0; pz < 8; pz++) {
                float a = o[2 * pz] * inv, b = o[2 * pz + 1] * inv;
                hw[pz] = phi(a, b);
                lw[pz] = plo(a, b, hw[pz]);
            }
            char* dh = XAH + row * RS + h * 32;
            char* dl = XAL + row * RS + h * 32;
            *reinterpret_cast<uint4*>(dh) = make_uint4(hw[0], hw[1], hw[2], hw[3]);
            *reinterpret_cast<uint4*>(dh + 16) = make_uint4(hw[4], hw[5], hw[6], hw[7]);
            *reinterpret_cast<uint4*>(dl) = make_uint4(lw[0], lw[1], lw[2], lw[3]);
            *reinterpret_cast<uint4*>(dl + 16) = make_uint4(lw[4], lw[5], lw[6], lw[7]);
        }
        __syncwarp();

        __syncthreads();   // all warps done with QKV weight slots
        // -------- phase B: stage Wo, W1, W2
        {
            const uint4* sH = reinterpret_cast<const uint4*>(g_wth + l * LAYER_ELEMS + 3 * SLOT_ELEMS);
            const uint4* sL = reinterpret_cast<const uint4*>(g_wtl + l * LAYER_ELEMS + 3 * SLOT_ELEMS);
            uint4* dH = reinterpret_cast<uint4*>(WTH);
            uint4* dL = reinterpret_cast<uint4*>(WTL);
            for (int i = tid; i < 1728; i += NT) { dH[i] = sH[i]; dL[i] = sL[i]; }
        }
        __syncthreads();

        // -------- o @ Wo + bo + x ; LN1
        {
            float acc[8][4];
#pragma unroll
            for (int nt = 0; nt < 8; nt++) { acc[nt][0] = acc[nt][1] = acc[nt][2] = acc[nt][3] = 0.f; }
            gemm_smem(XAH, XAL, WTH + 0 * SLOT, WTL + 0 * SLOT, acc, m0, r, j);
#pragma unroll
            for (int nt = 0; nt < 8; nt++) {
                int c = nt * 8 + j * 2;
                float2 bb = *reinterpret_cast<const float2*>(cst + c);
                x[nt][0] += acc[nt][0] + bb.x; x[nt][1] += acc[nt][1] + bb.y;
                x[nt][2] += acc[nt][2] + bb.x; x[nt][3] += acc[nt][3] + bb.y;
            }
            ln_frag(x, cst + 192, cst + 256, j);
        }

        // -------- FF1 -> relu -> FF2 -> residual -> LN2 (all regs)
        {
            float t1[8][4];
#pragma unroll
            for (int nt = 0; nt < 8; nt++) { t1[nt][0] = t1[nt][1] = t1[nt][2] = t1[nt][3] = 0.f; }
            gemm_reg<8>(x, WTH + 1 * SLOT, WTL + 1 * SLOT, t1, r, j);
#pragma unroll
            for (int nt = 0; nt < 8; nt++) {
                int c = nt * 8 + j * 2;
                float2 bb = *reinterpret_cast<const float2*>(cst + 64 + c);
                t1[nt][0] = fmaxf(t1[nt][0] + bb.x, 0.f); t1[nt][1] = fmaxf(t1[nt][1] + bb.y, 0.f);
                t1[nt][2] = fmaxf(t1[nt][2] + bb.x, 0.f); t1[nt][3] = fmaxf(t1[nt][3] + bb.y, 0.f);
            }
            float acc[8][4];
#pragma unroll
            for (int nt = 0; nt < 8; nt++) { acc[nt][0] = acc[nt][1] = acc[nt][2] = acc[nt][3] = 0.f; }
            gemm_reg<8>(t1, WTH + 2 * SLOT, WTL + 2 * SLOT, acc, r, j);
#pragma unroll
            for (int nt = 0; nt < 8; nt++) {
                int c = nt * 8 + j * 2;
                float2 bb = *reinterpret_cast<const float2*>(cst + 128 + c);
                x[nt][0] += acc[nt][0] + bb.x; x[nt][1] += acc[nt][1] + bb.y;
                x[nt][2] += acc[nt][2] + bb.x; x[nt][3] += acc[nt][3] + bb.y;
            }
            ln_frag(x, cst + 320, cst + 384, j);
        }
    }

    // -------- final projection
    __syncthreads();
    {
        const uint4* sH = reinterpret_cast<const uint4*>(g_wth + WOUT_OFF);
        const uint4* sL = reinterpret_cast<const uint4*>(g_wtl + WOUT_OFF);
        uint4* dH = reinterpret_cast<uint4*>(WTH);
        uint4* dL = reinterpret_cast<uint4*>(WTL);
        for (int i = tid; i < 864; i += NT) { dH[i] = sH[i]; dL[i] = sL[i]; }
        if (tid < 96) cst[tid] = bout[tid];
    }
    __syncthreads();
    {
        float acc[12][4];
#pragma unroll
        for (int nt = 0; nt < 12; nt++) { acc[nt][0] = acc[nt][1] = acc[nt][2] = acc[nt][3] = 0.f; }
        gemm_reg<12>(x, WTH, WTL, acc, r, j);
        float* o0 = out + (size_t)(blk * ROWS + m0 + r) * VOCAB;
        float* o1 = out + (size_t)(blk * ROWS + m0 + r + 8) * VOCAB;
#pragma unroll
        for (int nt = 0; nt < 12; nt++) {
            int c = nt * 8 + j * 2;
            float2 bb = *reinterpret_cast<const float2*>(cst + c);
            *reinterpret_cast<float2*>(o0 + c) = make_float2(acc[nt][0] + bb.x, acc[nt][1] + bb.y);
            *reinterpret_cast<float2*>(o1 + c) = make_float2(acc[nt][2] + bb.x, acc[nt][3] + bb.y);
        }
    }
}

extern "C" void kernel_launch(void* const* d_in, const int* in_sizes, int n_in,
                              void* d_out, int out_size) {
    const int*   data    = (const int*)d_in[0];
    const float* tok_emb = (const float*)d_in[1];
    const float* pos_emb = (const float*)d_in[2];
    const float* Wq      = (const float*)d_in[3];
    const float* Wk      = (const float*)d_in[4];
    const float* Wv      = (const float*)d_in[5];
    const float* Wo      = (const float*)d_in[6];
    const float* bo      = (const float*)d_in[7];
    const float* ln1g    = (const float*)d_in[8];
    const float* ln1b    = (const float*)d_in[9];
    const float* ln2g    = (const float*)d_in[10];
    const float* ln2b    = (const float*)d_in[11];
    const float* W1      = (const float*)d_in[12];
    const float* b1      = (const float*)d_in[13];
    const float* W2      = (const float*)d_in[14];
    const float* b2      = (const float*)d_in[15];
    const float* Wout    = (const float*)d_in[16];
    const float* bout    = (const float*)d_in[17];
    float* out = (float*)d_out;

    prep_kernel<<<(TOTAL_W + 255) / 256, 256>>>(Wq, Wk, Wv, Wo, W1, W2, Wout);
    cudaFuncSetAttribute(bert_mma_kernel,
                         cudaFuncAttributeMaxDynamicSharedMemorySize, SMEM_BYTES);
    bert_mma_kernel<<<BB / G, NT, SMEM_BYTES>>>(
        data, tok_emb, pos_emb, bo, ln1g, ln1b, ln2g, ln2b,
        b1, b2, bout, out);
}

// round 10
// speedup vs baseline: 2.3844x; 1.0597x over previous
#include <cuda_runtime.h>
#include <cuda_bf16.h>
#include <cstdint>

#define VOCAB 96
#define TT 16
#define EE 64
#define LL 4
#define BB 16384
#define G 4
#define ROWS 64
#define NT 128

#define RS 144            // bf16 row stride bytes for QH/KH/XA (72 bf16)
#define VSTR 72           // fp32 V row stride (floats)

// smem offsets (bytes)
#define O_CST  0
#define O_WPK  2048
#define O_XAH  (O_WPK + 16384)   // 18432
#define O_XAL  (O_XAH + 9216)    // 27648
#define O_QH   (O_XAL + 9216)    // 36864
#define O_KH   (O_QH  + 9216)    // 46080
#define O_VF   (O_KH  + 9216)    // 55296
#define SMEM_BYTES (O_VF + ROWS * VSTR * 4)   // 73728

#define TOTAL_UNITS (24 * 1024 + 1536)        // 26112 16B-units

__device__ __align__(16) uint4 g_wpk[TOTAL_UNITS];

// ---------------- helpers ----------------
__device__ __forceinline__ uint32_t phi(float a, float b) {
    __nv_bfloat162 t = __floats2bfloat162_rn(a, b);
    return *reinterpret_cast<uint32_t*>(&t);
}
__device__ __forceinline__ uint32_t plo(float a, float b, uint32_t h) {
    float2 f = __bfloat1622float2(*reinterpret_cast<__nv_bfloat162*>(&h));
    __nv_bfloat162 t = __floats2bfloat162_rn(a - f.x, b - f.y);
    return *reinterpret_cast<uint32_t*>(&t);
}
__device__ __forceinline__ void up2(uint32_t w, float* o) {
    float2 f = __bfloat1622float2(*reinterpret_cast<__nv_bfloat162*>(&w));
    o[0] = f.x; o[1] = f.y;
}
__device__ __forceinline__ void up8(const char* p, float* o) {
    uint4 u = *reinterpret_cast<const uint4*>(p);
    up2(u.x, o); up2(u.y, o + 2); up2(u.z, o + 4); up2(u.w, o + 6);
}
__device__ __forceinline__ void mma16816(float d[4], uint32_t a0, uint32_t a1,
                                         uint32_t a2, uint32_t a3,
                                         uint32_t b0, uint32_t b1) {
    asm volatile(
        "mma.sync.aligned.m16n8k16.row.col.f32.bf16.bf16.f32 "
        "{%0,%1,%2,%3}, {%4,%5,%6,%7}, {%8,%9}, {%0,%1,%2,%3};"
        : "+f"(d[0]), "+f"(d[1]), "+f"(d[2]), "+f"(d[3])
        : "r"(a0), "r"(a1), "r"(a2), "r"(a3), "r"(b0), "r"(b1));
}
// pack all 4 k-steps of an activation fragment set (hi+lo)
__device__ __forceinline__ void pack_frags(const float act[8][4],
                                           uint32_t ah[16], uint32_t al[16]) {
#pragma unroll
    for (int ks = 0; ks < 4; ks++) {
        const float* a0 = act[2 * ks];
        const float* a1 = act[2 * ks + 1];
        ah[4*ks+0] = phi(a0[0], a0[1]); al[4*ks+0] = plo(a0[0], a0[1], ah[4*ks+0]);
        ah[4*ks+1] = phi(a0[2], a0[3]); al[4*ks+1] = plo(a0[2], a0[3], ah[4*ks+1]);
        ah[4*ks+2] = phi(a1[0], a1[1]); al[4*ks+2] = plo(a1[0], a1[1], ah[4*ks+2]);
        ah[4*ks+3] = phi(a1[2], a1[3]); al[4*ks+3] = plo(a1[2], a1[3], ah[4*ks+3]);
    }
}
// GEMM with pre-packed A and packed weight units: unit(nt,ks,r,j) at ((nt*4+ks)*8+r)*4+j
template <int NTL>
__device__ __forceinline__ void gemm_pk(const uint32_t ah[16], const uint32_t al[16],
                                        const char* wpk, float acc[NTL][4],
                                        int r, int j) {
#pragma unroll
    for (int ks = 0; ks < 4; ks++) {
        const uint32_t* AH = ah + 4 * ks;
        const uint32_t* AL = al + 4 * ks;
#pragma unroll
        for (int nt = 0; nt < NTL; nt++) {
            uint4 b = *reinterpret_cast<const uint4*>(
                wpk + ((((nt * 4 + ks) * 8 + r) * 4 + j) << 4));
            mma16816(acc[nt], AH[0], AH[1], AH[2], AH[3], b.x, b.y);
            mma16816(acc[nt], AL[0], AL[1], AL[2], AL[3], b.x, b.y);
            mma16816(acc[nt], AH[0], AH[1], AH[2], AH[3], b.z, b.w);
        }
    }
}
// GEMM with A hi/lo in smem (o @ Wo)
__device__ __forceinline__ void gemm_sm(const char* xah, const char* xal,
                                        const char* wpk, float acc[8][4],
                                        int m0, int r, int j) {
#pragma unroll
    for (int ks = 0; ks < 4; ks++) {
        uint32_t off = (m0 + r) * RS + ks * 32 + j * 4;
        uint32_t ah0 = *reinterpret_cast<const uint32_t*>(xah + off);
        uint32_t ah1 = *reinterpret_cast<const uint32_t*>(xah + off + 8 * RS);
        uint32_t ah2 = *reinterpret_cast<const uint32_t*>(xah + off + 16);
        uint32_t ah3 = *reinterpret_cast<const uint32_t*>(xah + off + 8 * RS + 16);
        uint32_t al0 = *reinterpret_cast<const uint32_t*>(xal + off);
        uint32_t al1 = *reinterpret_cast<const uint32_t*>(xal + off + 8 * RS);
        uint32_t al2 = *reinterpret_cast<const uint32_t*>(xal + off + 16);
        uint32_t al3 = *reinterpret_cast<const uint32_t*>(xal + off + 8 * RS + 16);
#pragma unroll
        for (int nt = 0; nt < 8; nt++) {
            uint4 b = *reinterpret_cast<const uint4*>(
                wpk + ((((nt * 4 + ks) * 8 + r) * 4 + j) << 4));
            mma16816(acc[nt], ah0, ah1, ah2, ah3, b.x, b.y);
            mma16816(acc[nt], al0, al1, al2, al3, b.x, b.y);
            mma16816(acc[nt], ah0, ah1, ah2, ah3, b.z, b.w);
        }
    }
}
__device__ __forceinline__ void fstore_hi(char* B, int m0, int r, int j,
                                          const float a[8][4]) {
#pragma unroll
    for (int nt = 0; nt < 8; nt++) {
        uint32_t co = (uint32_t)(nt * 16 + j * 4);
        *reinterpret_cast<uint32_t*>(B + (m0 + r) * RS + co) = phi(a[nt][0], a[nt][1]);
        *reinterpret_cast<uint32_t*>(B + (m0 + r + 8) * RS + co) = phi(a[nt][2], a[nt][3]);
    }
}
__device__ __forceinline__ void fstore_f32(float* V, int m0, int r, int j,
                                           const float a[8][4]) {
#pragma unroll
    for (int nt = 0; nt < 8; nt++) {
        int c = nt * 8 + j * 2;
        *reinterpret_cast<float2*>(V + (m0 + r) * VSTR + c) = make_float2(a[nt][0], a[nt][1]);
        *reinterpret_cast<float2*>(V + (m0 + r + 8) * VSTR + c) = make_float2(a[nt][2], a[nt][3]);
    }
}
__device__ __forceinline__ void ln_frag(float x[8][4], const float* g, const float* b, int j) {
    float s0 = 0.f, q0 = 0.f, s1 = 0.f, q1 = 0.f;
#pragma unroll
    for (int nt = 0; nt < 8; nt++) {
        s0 += x[nt][0] + x[nt][1]; q0 += x[nt][0] * x[nt][0] + x[nt][1] * x[nt][1];
        s1 += x[nt][2] + x[nt][3]; q1 += x[nt][2] * x[nt][2] + x[nt][3] * x[nt][3];
    }
    s0 += __shfl_xor_sync(0xffffffffu, s0, 1); q0 += __shfl_xor_sync(0xffffffffu, q0, 1);
    s1 += __shfl_xor_sync(0xffffffffu, s1, 1); q1 += __shfl_xor_sync(0xffffffffu, q1, 1);
    s0 += __shfl_xor_sync(0xffffffffu, s0, 2); q0 += __shfl_xor_sync(0xffffffffu, q0, 2);
    s1 += __shfl_xor_sync(0xffffffffu, s1, 2); q1 += __shfl_xor_sync(0xffffffffu, q1, 2);
    float m0 = s0 * (1.f / 64.f), m1 = s1 * (1.f / 64.f);
    float r0 = rsqrtf(q0 * (1.f / 64.f) - m0 * m0 + 1e-5f);
    float r1 = rsqrtf(q1 * (1.f / 64.f) - m1 * m1 + 1e-5f);
#pragma unroll
    for (int nt = 0; nt < 8; nt++) {
        int c = nt * 8 + j * 2;
        float2 gg = *reinterpret_cast<const float2*>(g + c);
        float2 bb = *reinterpret_cast<const float2*>(b + c);
        x[nt][0] = (x[nt][0] - m0) * r0 * gg.x + bb.x;
        x[nt][1] = (x[nt][1] - m0) * r0 * gg.y + bb.y;
        x[nt][2] = (x[nt][2] - m1) * r1 * gg.x + bb.x;
        x[nt][3] = (x[nt][3] - m1) * r1 * gg.y + bb.y;
    }
}
__device__ __forceinline__ void stage_units(char* dst, int unit0, int n) {
    const uint4* s = g_wpk + unit0;
    uint4* d = reinterpret_cast<uint4*>(dst);
    for (int i = threadIdx.x; i < n; i += NT) d[i] = s[i];
}

// ---------------- prep kernel: pack weight fragments ----------------
__global__ void prep_kernel(const float* __restrict__ Wq, const float* __restrict__ Wk,
                            const float* __restrict__ Wv, const float* __restrict__ Wo,
                            const float* __restrict__ W1, const float* __restrict__ W2,
                            const float* __restrict__ Wout) {
    int gid = blockIdx.x * 256 + threadIdx.x;
    if (gid >= TOTAL_UNITS) return;
    int u, c, k0;
    float v00, v01, v80, v81;
    if (gid < 24 * 1024) {
        int sidx = gid >> 10;
        u = gid & 1023;
        int l = sidx / 6, slot = sidx % 6;
        int nt = u >> 7, ks = (u >> 5) & 3, r = (u >> 2) & 7, j = u & 3;
        c = nt * 8 + r;
        k0 = ks * 16 + j * 2;
        if (slot < 3) {
            const float* W = (slot == 0) ? Wq : (slot == 1) ? Wk : Wv;
            const float* p = W + l * 4096 + (c >> 4) * 1024 + (c & 15);
            v00 = p[k0 * 16]; v01 = p[(k0 + 1) * 16];
            v80 = p[(k0 + 8) * 16]; v81 = p[(k0 + 9) * 16];
        } else {
            const float* W = (slot == 3) ? Wo : (slot == 4) ? W1 : W2;
            const float* p = W + l * 4096 + c;
            v00 = p[k0 * 64]; v01 = p[(k0 + 1) * 64];
            v80 = p[(k0 + 8) * 64]; v81 = p[(k0 + 9) * 64];
        }
    } else {
        u = gid - 24 * 1024;
        int nt = u >> 7, ks = (u >> 5) & 3, r = (u >> 2) & 7, j = u & 3;
        c = nt * 8 + r;
        k0 = ks * 16 + j * 2;
        const float* p = Wout + c;
        v00 = p[k0 * 96]; v01 = p[(k0 + 1) * 96];
        v80 = p[(k0 + 8) * 96]; v81 = p[(k0 + 9) * 96];
    }
    uint32_t h0 = phi(v00, v01), h8 = phi(v80, v81);
    uint32_t l0 = plo(v00, v01, h0), l8 = plo(v80, v81, h8);
    g_wpk[gid] = make_uint4(h0, h8, l0, l8);
}

// ---------------- main kernel ----------------
__global__ void __launch_bounds__(NT, 3)
bert_mma_kernel(const int* __restrict__ data, const float* __restrict__ tok_emb,
                const float* __restrict__ pos_emb,
                const float* __restrict__ bo,
                const float* __restrict__ ln1g, const float* __restrict__ ln1b,
                const float* __restrict__ ln2g, const float* __restrict__ ln2b,
                const float* __restrict__ b1, const float* __restrict__ b2,
                const float* __restrict__ bout, float* __restrict__ out) {
    extern __shared__ char sm[];
    float* cst = reinterpret_cast<float*>(sm + O_CST);
    char* WPK = sm + O_WPK;
    char* XAH = sm + O_XAH; char* XAL = sm + O_XAL;
    char* QH = sm + O_QH;  char* KH = sm + O_KH;
    float* VF = reinterpret_cast<float*>(sm + O_VF);

    const int tid = threadIdx.x;
    const int w = tid >> 5, lane = tid & 31;
    const int r = lane >> 2, j = lane & 3;
    const int m0 = w * 16;
    const int blk = blockIdx.x;

    // -------- embedding (fragment layout)
    float x[8][4];
    {
        int b = blk * G + w;
        int tokA = data[b * TT + r], tokB = data[b * TT + r + 8];
#pragma unroll
        for (int nt = 0; nt < 8; nt++) {
            int c = nt * 8 + j * 2;
            float2 tA = *reinterpret_cast<const float2*>(tok_emb + tokA * EE + c);
            float2 tB = *reinterpret_cast<const float2*>(tok_emb + tokB * EE + c);
            float2 pA = *reinterpret_cast<const float2*>(pos_emb + r * EE + c);
            float2 pB = *reinterpret_cast<const float2*>(pos_emb + (r + 8) * EE + c);
            x[nt][0] = tA.x + pA.x; x[nt][1] = tA.y + pA.y;
            x[nt][2] = tB.x + pB.x; x[nt][3] = tB.y + pB.y;
        }
    }

    for (int l = 0; l < LL; l++) {
        const int base = l * 6 * 1024;
        __syncthreads();                       // prior WPK reads complete
        stage_units(WPK, base + 0, 1024);      // Wq
        if (tid < 64) {
            cst[tid] = bo[l * 64 + tid];         cst[64 + tid] = b1[l * 64 + tid];
            cst[128 + tid] = b2[l * 64 + tid];   cst[192 + tid] = ln1g[l * 64 + tid];
            cst[256 + tid] = ln1b[l * 64 + tid]; cst[320 + tid] = ln2g[l * 64 + tid];
            cst[384 + tid] = ln2b[l * 64 + tid];
        }
        __syncthreads();

        // pack x fragments once for Q/K/V
        uint32_t pah[16], pal[16];
        pack_frags(x, pah, pal);

        {   // Q
            float acc[8][4];
#pragma unroll
            for (int nt = 0; nt < 8; nt++) { acc[nt][0] = acc[nt][1] = acc[nt][2] = acc[nt][3] = 0.f; }
            gemm_pk<8>(pah, pal, WPK, acc, r, j);
            fstore_hi(QH, m0, r, j, acc);
        }
        __syncthreads();
        stage_units(WPK, base + 1024, 1024);   // Wk
        __syncthreads();
        {   // K
            float acc[8][4];
#pragma unroll
            for (int nt = 0; nt < 8; nt++) { acc[nt][0] = acc[nt][1] = acc[nt][2] = acc[nt][3] = 0.f; }
            gemm_pk<8>(pah, pal, WPK, acc, r, j);
            fstore_hi(KH, m0, r, j, acc);
        }
        __syncthreads();
        stage_units(WPK, base + 2048, 1024);   // Wv
        __syncthreads();
        {   // V
            float acc[8][4];
#pragma unroll
            for (int nt = 0; nt < 8; nt++) { acc[nt][0] = acc[nt][1] = acc[nt][2] = acc[nt][3] = 0.f; }
            gemm_pk<8>(pah, pal, WPK, acc, r, j);
            fstore_f32(VF, m0, r, j, acc);
        }
        __syncwarp();

        // -------- attention (warp-private)
#pragma unroll
        for (int it = 0; it < 2; it++) {
            int h = ((lane >> 4) << 1) | it;
            int t = lane & 15;
            int row = m0 + t;
            float q[16];
            up8(QH + row * RS + h * 32, q);
            up8(QH + row * RS + h * 32 + 16, q + 8);
            float p[16], mx = -1e30f;
#pragma unroll
            for (int s = 0; s < 16; s++) {
                float kk[16];
                up8(KH + (m0 + s) * RS + h * 32, kk);
                up8(KH + (m0 + s) * RS + h * 32 + 16, kk + 8);
                float a = 0.f;
#pragma unroll
                for (int i = 0; i < 16; i++) a += q[i] * kk[i];
                a *= 0.25f;
                p[s] = a; mx = fmaxf(mx, a);
            }
            float sum = 0.f;
#pragma unroll
            for (int s = 0; s < 16; s++) { p[s] = __expf(p[s] - mx); sum += p[s]; }
            float inv = 1.f / sum;
            float o[16];
#pragma unroll
            for (int i = 0; i < 16; i++) o[i] = 0.f;
#pragma unroll
            for (int s = 0; s < 16; s++) {
                const float4* v4 = reinterpret_cast<const float4*>(VF + (m0 + s) * VSTR + h * 16);
                float4 a0 = v4[0], a1 = v4[1], a2 = v4[2], a3 = v4[3];
                float ps = p[s];
                o[0] += ps * a0.x; o[1] += ps * a0.y; o[2] += ps * a0.z; o[3] += ps * a0.w;
                o[4] += ps * a1.x; o[5] += ps * a1.y; o[6] += ps * a1.z; o[7] += ps * a1.w;
                o[8] += ps * a2.x; o[9] += ps * a2.y; o[10] += ps * a2.z; o[11] += ps * a2.w;
                o[12] += ps * a3.x; o[13] += ps * a3.y; o[14] += ps * a3.z; o[15] += ps * a3.w;
            }
            uint32_t hw[8], lw[8];
#pragma unroll
            for (int pz = 0; pz < 8; pz++) {
                float a = o[2 * pz] * inv, b = o[2 * pz + 1] * inv;
                hw[pz] = phi(a, b);
                lw[pz] = plo(a, b, hw[pz]);
            }
            char* dh = XAH + row * RS + h * 32;
            char* dl = XAL + row * RS + h * 32;
            *reinterpret_cast<uint4*>(dh) = make_uint4(hw[0], hw[1], hw[2], hw[3]);
            *reinterpret_cast<uint4*>(dh + 16) = make_uint4(hw[4], hw[5], hw[6], hw[7]);
            *reinterpret_cast<uint4*>(dl) = make_uint4(lw[0], lw[1], lw[2], lw[3]);
            *reinterpret_cast<uint4*>(dl + 16) = make_uint4(lw[4], lw[5], lw[6], lw[7]);
        }
        __syncthreads();
        stage_units(WPK, base + 3072, 1024);   // Wo
        __syncthreads();

        // -------- o @ Wo + bo + x ; LN1
        {
            float acc[8][4];
#pragma unroll
            for (int nt = 0; nt < 8; nt++) { acc[nt][0] = acc[nt][1] = acc[nt][2] = acc[nt][3] = 0.f; }
            gemm_sm(XAH, XAL, WPK, acc, m0, r, j);
#pragma unroll
            for (int nt = 0; nt < 8; nt++) {
                int c = nt * 8 + j * 2;
                float2 bb = *reinterpret_cast<const float2*>(cst + c);
                x[nt][0] += acc[nt][0] + bb.x; x[nt][1] += acc[nt][1] + bb.y;
                x[nt][2] += acc[nt][2] + bb.x; x[nt][3] += acc[nt][3] + bb.y;
            }
            ln_frag(x, cst + 192, cst + 256, j);
        }
        __syncthreads();
        stage_units(WPK, base + 4096, 1024);   // W1
        __syncthreads();

        // -------- FF1
        float t1[8][4];
        {
            uint32_t fah[16], fal[16];
            pack_frags(x, fah, fal);
#pragma unroll
            for (int nt = 0; nt < 8; nt++) { t1[nt][0] = t1[nt][1] = t1[nt][2] = t1[nt][3] = 0.f; }
            gemm_pk<8>(fah, fal, WPK, t1, r, j);
#pragma unroll
            for (int nt = 0; nt < 8; nt++) {
                int c = nt * 8 + j * 2;
                float2 bb = *reinterpret_cast<const float2*>(cst + 64 + c);
                t1[nt][0] = fmaxf(t1[nt][0] + bb.x, 0.f); t1[nt][1] = fmaxf(t1[nt][1] + bb.y, 0.f);
                t1[nt][2] = fmaxf(t1[nt][2] + bb.x, 0.f); t1[nt][3] = fmaxf(t1[nt][3] + bb.y, 0.f);
            }
        }
        __syncthreads();
        stage_units(WPK, base + 5120, 1024);   // W2
        __syncthreads();

        // -------- FF2 + residual + LN2
        {
            uint32_t fah[16], fal[16];
            pack_frags(t1, fah, fal);
            float acc[8][4];
#pragma unroll
            for (int nt = 0; nt < 8; nt++) { acc[nt][0] = acc[nt][1] = acc[nt][2] = acc[nt][3] = 0.f; }
            gemm_pk<8>(fah, fal, WPK, acc, r, j);
#pragma unroll
            for (int nt = 0; nt < 8; nt++) {
                int c = nt * 8 + j * 2;
                float2 bb = *reinterpret_cast<const float2*>(cst + 128 + c);
                x[nt][0] += acc[nt][0] + bb.x; x[nt][1] += acc[nt][1] + bb.y;
                x[nt][2] += acc[nt][2] + bb.x; x[nt][3] += acc[nt][3] + bb.y;
            }
            ln_frag(x, cst + 320, cst + 384, j);
        }
    }

    // -------- final projection (Wout packed units staged into XAH region)
    __syncthreads();
    stage_units(sm + O_XAH, 24 * 1024, 1536);
    if (tid < 96) cst[tid] = bout[tid];
    __syncthreads();
    {
        uint32_t fah[16], fal[16];
        pack_frags(x, fah, fal);
        float acc[12][4];
#pragma unroll
        for (int nt = 0; nt < 12; nt++) { acc[nt][0] = acc[nt][1] = acc[nt][2] = acc[nt][3] = 0.f; }
        gemm_pk<12>(fah, fal, sm + O_XAH, acc, r, j);
        float* o0 = out + (size_t)(blk * ROWS + m0 + r) * VOCAB;
        float* o1 = out + (size_t)(blk * ROWS + m0 + r + 8) * VOCAB;
#pragma unroll
        for (int nt = 0; nt < 12; nt++) {
            int c = nt * 8 + j * 2;
            float2 bb = *reinterpret_cast<const float2*>(cst + c);
            *reinterpret_cast<float2*>(o0 + c) = make_float2(acc[nt][0] + bb.x, acc[nt][1] + bb.y);
            *reinterpret_cast<float2*>(o1 + c) = make_float2(acc[nt][2] + bb.x, acc[nt][3] + bb.y);
        }
    }
}

extern "C" void kernel_launch(void* const* d_in, const int* in_sizes, int n_in,
                              void* d_out, int out_size) {
    const int*   data    = (const int*)d_in[0];
    const float* tok_emb = (const float*)d_in[1];
    const float* pos_emb = (const float*)d_in[2];
    const float* Wq      = (const float*)d_in[3];
    const float* Wk      = (const float*)d_in[4];
    const float* Wv      = (const float*)d_in[5];
    const float* Wo      = (const float*)d_in[6];
    const float* bo      = (const float*)d_in[7];
    const float* ln1g    = (const float*)d_in[8];
    const float* ln1b    = (const float*)d_in[9];
    const float* ln2g    = (const float*)d_in[10];
    const float* ln2b    = (const float*)d_in[11];
    const float* W1      = (const float*)d_in[12];
    const float* b1      = (const float*)d_in[13];
    const float* W2      = (const float*)d_in[14];
    const float* b2      = (const float*)d_in[15];
    const float* Wout    = (const float*)d_in[16];
    const float* bout    = (const float*)d_in[17];
    float* out = (float*)d_out;

    prep_kernel<<<(TOTAL_UNITS + 255) / 256, 256>>>(Wq, Wk, Wv, Wo, W1, W2, Wout);
    cudaFuncSetAttribute(bert_mma_kernel,
                         cudaFuncAttributeMaxDynamicSharedMemorySize, SMEM_BYTES);
    bert_mma_kernel<<<BB / G, NT, SMEM_BYTES>>>(
        data, tok_emb, pos_emb, bo, ln1g, ln1b, ln2g, ln2b,
        b1, b2, bout, out);
}

// round 11
// speedup vs baseline: 2.6225x; 1.0998x over previous
#include <cuda_runtime.h>
#include <cuda_bf16.h>
#include <cstdint>

#define VOCAB 96
#define TT 16
#define EE 64
#define LL 4
#define BB 16384
#define G 4
#define ROWS 64
#define NT 128

#define RS 144            // bf16 row stride bytes for QH/KH/XAH (72 bf16)
#define VSTR 72           // fp32 V row stride (floats)

// smem offsets (bytes) — all warp-private rows
#define O_XAH  0
#define O_QH   9216
#define O_KH   18432
#define O_VF   27648
#define SMEM_BYTES (O_VF + ROWS * VSTR * 4)   // 46080

#define TOTAL_UNITS (24 * 1024 + 1536)

__device__ __align__(16) uint4 g_wpk[TOTAL_UNITS];

// ---------------- helpers ----------------
__device__ __forceinline__ uint32_t phi(float a, float b) {
    __nv_bfloat162 t = __floats2bfloat162_rn(a, b);
    return *reinterpret_cast<uint32_t*>(&t);
}
__device__ __forceinline__ uint32_t plo(float a, float b, uint32_t h) {
    float2 f = __bfloat1622float2(*reinterpret_cast<__nv_bfloat162*>(&h));
    __nv_bfloat162 t = __floats2bfloat162_rn(a - f.x, b - f.y);
    return *reinterpret_cast<uint32_t*>(&t);
}
__device__ __forceinline__ void up2(uint32_t w, float* o) {
    float2 f = __bfloat1622float2(*reinterpret_cast<__nv_bfloat162*>(&w));
    o[0] = f.x; o[1] = f.y;
}
__device__ __forceinline__ void up8(const char* p, float* o) {
    uint4 u = *reinterpret_cast<const uint4*>(p);
    up2(u.x, o); up2(u.y, o + 2); up2(u.z, o + 4); up2(u.w, o + 6);
}
__device__ __forceinline__ void mma16816(float d[4], uint32_t a0, uint32_t a1,
                                         uint32_t a2, uint32_t a3,
                                         uint32_t b0, uint32_t b1) {
    asm volatile(
        "mma.sync.aligned.m16n8k16.row.col.f32.bf16.bf16.f32 "
        "{%0,%1,%2,%3}, {%4,%5,%6,%7}, {%8,%9}, {%0,%1,%2,%3};"
        : "+f"(d[0]), "+f"(d[1]), "+f"(d[2]), "+f"(d[3])
        : "r"(a0), "r"(a1), "r"(a2), "r"(a3), "r"(b0), "r"(b1));
}
__device__ __forceinline__ void pack_frags(const float act[8][4],
                                           uint32_t ah[16], uint32_t al[16]) {
#pragma unroll
    for (int ks = 0; ks < 4; ks++) {
        const float* a0 = act[2 * ks];
        const float* a1 = act[2 * ks + 1];
        ah[4*ks+0] = phi(a0[0], a0[1]); al[4*ks+0] = plo(a0[0], a0[1], ah[4*ks+0]);
        ah[4*ks+1] = phi(a0[2], a0[3]); al[4*ks+1] = plo(a0[2], a0[3], ah[4*ks+1]);
        ah[4*ks+2] = phi(a1[0], a1[1]); al[4*ks+2] = plo(a1[0], a1[1], ah[4*ks+2]);
        ah[4*ks+3] = phi(a1[2], a1[3]); al[4*ks+3] = plo(a1[2], a1[3], ah[4*ks+3]);
    }
}
// GEMM: pre-packed A (hi+lo regs) x packed weights in GLOBAL (3-term split)
template <int NTL>
__device__ __forceinline__ void gemm_pk(const uint32_t ah[16], const uint32_t al[16],
                                        const uint4* __restrict__ wu,
                                        float acc[NTL][4], int r, int j) {
#pragma unroll
    for (int ks = 0; ks < 4; ks++) {
        const uint32_t* AH = ah + 4 * ks;
        const uint32_t* AL = al + 4 * ks;
#pragma unroll
        for (int nt = 0; nt < NTL; nt++) {
            uint4 b = __ldg(wu + ((nt * 4 + ks) * 8 + r) * 4 + j);
            mma16816(acc[nt], AH[0], AH[1], AH[2], AH[3], b.x, b.y);
            mma16816(acc[nt], AL[0], AL[1], AL[2], AL[3], b.x, b.y);
            mma16816(acc[nt], AH[0], AH[1], AH[2], AH[3], b.z, b.w);
        }
    }
}
// o @ Wo: A hi-only from smem (2-term: Ah*Bh + Ah*Bl)
__device__ __forceinline__ void gemm_o(const char* xah, const uint4* __restrict__ wu,
                                       float acc[8][4], int m0, int r, int j) {
#pragma unroll
    for (int ks = 0; ks < 4; ks++) {
        uint32_t off = (m0 + r) * RS + ks * 32 + j * 4;
        uint32_t a0 = *reinterpret_cast<const uint32_t*>(xah + off);
        uint32_t a1 = *reinterpret_cast<const uint32_t*>(xah + off + 8 * RS);
        uint32_t a2 = *reinterpret_cast<const uint32_t*>(xah + off + 16);
        uint32_t a3 = *reinterpret_cast<const uint32_t*>(xah + off + 8 * RS + 16);
#pragma unroll
        for (int nt = 0; nt < 8; nt++) {
            uint4 b = __ldg(wu + ((nt * 4 + ks) * 8 + r) * 4 + j);
            mma16816(acc[nt], a0, a1, a2, a3, b.x, b.y);
            mma16816(acc[nt], a0, a1, a2, a3, b.z, b.w);
        }
    }
}
__device__ __forceinline__ void fstore_hi(char* B, int m0, int r, int j,
                                          const float a[8][4]) {
#pragma unroll
    for (int nt = 0; nt < 8; nt++) {
        uint32_t co = (uint32_t)(nt * 16 + j * 4);
        *reinterpret_cast<uint32_t*>(B + (m0 + r) * RS + co) = phi(a[nt][0], a[nt][1]);
        *reinterpret_cast<uint32_t*>(B + (m0 + r + 8) * RS + co) = phi(a[nt][2], a[nt][3]);
    }
}
__device__ __forceinline__ void fstore_f32(float* V, int m0, int r, int j,
                                           const float a[8][4]) {
#pragma unroll
    for (int nt = 0; nt < 8; nt++) {
        int c = nt * 8 + j * 2;
        *reinterpret_cast<float2*>(V + (m0 + r) * VSTR + c) = make_float2(a[nt][0], a[nt][1]);
        *reinterpret_cast<float2*>(V + (m0 + r + 8) * VSTR + c) = make_float2(a[nt][2], a[nt][3]);
    }
}
__device__ __forceinline__ void ln_frag(float x[8][4], const float* __restrict__ g,
                                        const float* __restrict__ b, int j) {
    float s0 = 0.f, q0 = 0.f, s1 = 0.f, q1 = 0.f;
#pragma unroll
    for (int nt = 0; nt < 8; nt++) {
        s0 += x[nt][0] + x[nt][1]; q0 += x[nt][0] * x[nt][0] + x[nt][1] * x[nt][1];
        s1 += x[nt][2] + x[nt][3]; q1 += x[nt][2] * x[nt][2] + x[nt][3] * x[nt][3];
    }
    s0 += __shfl_xor_sync(0xffffffffu, s0, 1); q0 += __shfl_xor_sync(0xffffffffu, q0, 1);
    s1 += __shfl_xor_sync(0xffffffffu, s1, 1); q1 += __shfl_xor_sync(0xffffffffu, q1, 1);
    s0 += __shfl_xor_sync(0xffffffffu, s0, 2); q0 += __shfl_xor_sync(0xffffffffu, q0, 2);
    s1 += __shfl_xor_sync(0xffffffffu, s1, 2); q1 += __shfl_xor_sync(0xffffffffu, q1, 2);
    float m0 = s0 * (1.f / 64.f), m1 = s1 * (1.f / 64.f);
    float r0 = rsqrtf(q0 * (1.f / 64.f) - m0 * m0 + 1e-5f);
    float r1 = rsqrtf(q1 * (1.f / 64.f) - m1 * m1 + 1e-5f);
#pragma unroll
    for (int nt = 0; nt < 8; nt++) {
        int c = nt * 8 + j * 2;
        float2 gg = __ldg(reinterpret_cast<const float2*>(g + c));
        float2 bb = __ldg(reinterpret_cast<const float2*>(b + c));
        x[nt][0] = (x[nt][0] - m0) * r0 * gg.x + bb.x;
        x[nt][1] = (x[nt][1] - m0) * r0 * gg.y + bb.y;
        x[nt][2] = (x[nt][2] - m1) * r1 * gg.x + bb.x;
        x[nt][3] = (x[nt][3] - m1) * r1 * gg.y + bb.y;
    }
}

// ---------------- prep kernel: pack weight fragments (unchanged layout) ----------------
__global__ void prep_kernel(const float* __restrict__ Wq, const float* __restrict__ Wk,
                            const float* __restrict__ Wv, const float* __restrict__ Wo,
                            const float* __restrict__ W1, const float* __restrict__ W2,
                            const float* __restrict__ Wout) {
    int gid = blockIdx.x * 256 + threadIdx.x;
    if (gid >= TOTAL_UNITS) return;
    int u, c, k0;
    float v00, v01, v80, v81;
    if (gid < 24 * 1024) {
        int sidx = gid >> 10;
        u = gid & 1023;
        int l = sidx / 6, slot = sidx % 6;
        int nt = u >> 7, ks = (u >> 5) & 3, r = (u >> 2) & 7, j = u & 3;
        c = nt * 8 + r;
        k0 = ks * 16 + j * 2;
        if (slot < 3) {
            const float* W = (slot == 0) ? Wq : (slot == 1) ? Wk : Wv;
            const float* p = W + l * 4096 + (c >> 4) * 1024 + (c & 15);
            v00 = p[k0 * 16]; v01 = p[(k0 + 1) * 16];
            v80 = p[(k0 + 8) * 16]; v81 = p[(k0 + 9) * 16];
        } else {
            const float* W = (slot == 3) ? Wo : (slot == 4) ? W1 : W2;
            const float* p = W + l * 4096 + c;
            v00 = p[k0 * 64]; v01 = p[(k0 + 1) * 64];
            v80 = p[(k0 + 8) * 64]; v81 = p[(k0 + 9) * 64];
        }
    } else {
        u = gid - 24 * 1024;
        int nt = u >> 7, ks = (u >> 5) & 3, r = (u >> 2) & 7, j = u & 3;
        c = nt * 8 + r;
        k0 = ks * 16 + j * 2;
        const float* p = Wout + c;
        v00 = p[k0 * 96]; v01 = p[(k0 + 1) * 96];
        v80 = p[(k0 + 8) * 96]; v81 = p[(k0 + 9) * 96];
    }
    uint32_t h0 = phi(v00, v01), h8 = phi(v80, v81);
    uint32_t l0 = plo(v00, v01, h0), l8 = plo(v80, v81, h8);
    g_wpk[gid] = make_uint4(h0, h8, l0, l8);
}

// ---------------- main kernel: zero __syncthreads, warps fully decoupled ----------------
__global__ void __launch_bounds__(NT, 3)
bert_mma_kernel(const int* __restrict__ data, const float* __restrict__ tok_emb,
                const float* __restrict__ pos_emb,
                const float* __restrict__ bo,
                const float* __restrict__ ln1g, const float* __restrict__ ln1b,
                const float* __restrict__ ln2g, const float* __restrict__ ln2b,
                const float* __restrict__ b1, const float* __restrict__ b2,
                const float* __restrict__ bout, float* __restrict__ out) {
    extern __shared__ char sm[];
    char* XAH = sm + O_XAH;
    char* QH = sm + O_QH;  char* KH = sm + O_KH;
    float* VF = reinterpret_cast<float*>(sm + O_VF);

    const int tid = threadIdx.x;
    const int w = tid >> 5, lane = tid & 31;
    const int r = lane >> 2, j = lane & 3;
    const int m0 = w * 16;
    const int blk = blockIdx.x;

    // -------- embedding (fragment layout)
    float x[8][4];
    {
        int b = blk * G + w;
        int tokA = data[b * TT + r], tokB = data[b * TT + r + 8];
#pragma unroll
        for (int nt = 0; nt < 8; nt++) {
            int c = nt * 8 + j * 2;
            float2 tA = __ldg(reinterpret_cast<const float2*>(tok_emb + tokA * EE + c));
            float2 tB = __ldg(reinterpret_cast<const float2*>(tok_emb + tokB * EE + c));
            float2 pA = __ldg(reinterpret_cast<const float2*>(pos_emb + r * EE + c));
            float2 pB = __ldg(reinterpret_cast<const float2*>(pos_emb + (r + 8) * EE + c));
            x[nt][0] = tA.x + pA.x; x[nt][1] = tA.y + pA.y;
            x[nt][2] = tB.x + pB.x; x[nt][3] = tB.y + pB.y;
        }
    }

    for (int l = 0; l < LL; l++) {
        const uint4* wl = g_wpk + l * 6 * 1024;

        // pack x once for Q/K/V
        uint32_t pah[16], pal[16];
        pack_frags(x, pah, pal);

        {   // Q
            float acc[8][4];
#pragma unroll
            for (int nt = 0; nt < 8; nt++) { acc[nt][0] = acc[nt][1] = acc[nt][2] = acc[nt][3] = 0.f; }
            gemm_pk<8>(pah, pal, wl + 0, acc, r, j);
            fstore_hi(QH, m0, r, j, acc);
        }
        {   // K
            float acc[8][4];
#pragma unroll
            for (int nt = 0; nt < 8; nt++) { acc[nt][0] = acc[nt][1] = acc[nt][2] = acc[nt][3] = 0.f; }
            gemm_pk<8>(pah, pal, wl + 1024, acc, r, j);
            fstore_hi(KH, m0, r, j, acc);
        }
        {   // V
            float acc[8][4];
#pragma unroll
            for (int nt = 0; nt < 8; nt++) { acc[nt][0] = acc[nt][1] = acc[nt][2] = acc[nt][3] = 0.f; }
            gemm_pk<8>(pah, pal, wl + 2048, acc, r, j);
            fstore_f32(VF, m0, r, j, acc);
        }
        __syncwarp();

        // -------- attention (warp-private rows)
#pragma unroll
        for (int it = 0; it < 2; it++) {
            int h = ((lane >> 4) << 1) | it;
            int t = lane & 15;
            int row = m0 + t;
            float q[16];
            up8(QH + row * RS + h * 32, q);
            up8(QH + row * RS + h * 32 + 16, q + 8);
            float p[16], mx = -1e30f;
#pragma unroll
            for (int s = 0; s < 16; s++) {
                float kk[16];
                up8(KH + (m0 + s) * RS + h * 32, kk);
                up8(KH + (m0 + s) * RS + h * 32 + 16, kk + 8);
                float a = 0.f;
#pragma unroll
                for (int i = 0; i < 16; i++) a += q[i] * kk[i];
                a *= 0.25f;
                p[s] = a; mx = fmaxf(mx, a);
            }
            float sum = 0.f;
#pragma unroll
            for (int s = 0; s < 16; s++) { p[s] = __expf(p[s] - mx); sum += p[s]; }
            float inv = 1.f / sum;
            float o[16];
#pragma unroll
            for (int i = 0; i < 16; i++) o[i] = 0.f;
#pragma unroll
            for (int s = 0; s < 16; s++) {
                const float4* v4 = reinterpret_cast<const float4*>(VF + (m0 + s) * VSTR + h * 16);
                float4 a0 = v4[0], a1 = v4[1], a2 = v4[2], a3 = v4[3];
                float ps = p[s];
                o[0] += ps * a0.x; o[1] += ps * a0.y; o[2] += ps * a0.z; o[3] += ps * a0.w;
                o[4] += ps * a1.x; o[5] += ps * a1.y; o[6] += ps * a1.z; o[7] += ps * a1.w;
                o[8] += ps * a2.x; o[9] += ps * a2.y; o[10] += ps * a2.z; o[11] += ps * a2.w;
                o[12] += ps * a3.x; o[13] += ps * a3.y; o[14] += ps * a3.z; o[15] += ps * a3.w;
            }
            uint32_t hw[8];
#pragma unroll
            for (int pz = 0; pz < 8; pz++)
                hw[pz] = phi(o[2 * pz] * inv, o[2 * pz + 1] * inv);
            char* dh = XAH + row * RS + h * 32;
            *reinterpret_cast<uint4*>(dh) = make_uint4(hw[0], hw[1], hw[2], hw[3]);
            *reinterpret_cast<uint4*>(dh + 16) = make_uint4(hw[4], hw[5], hw[6], hw[7]);
        }
        __syncwarp();

        // -------- o @ Wo + bo + x ; LN1
        {
            float acc[8][4];
#pragma unroll
            for (int nt = 0; nt < 8; nt++) { acc[nt][0] = acc[nt][1] = acc[nt][2] = acc[nt][3] = 0.f; }
            gemm_o(XAH, wl + 3072, acc, m0, r, j);
#pragma unroll
            for (int nt = 0; nt < 8; nt++) {
                int c = nt * 8 + j * 2;
                float2 bb = __ldg(reinterpret_cast<const float2*>(bo + l * 64 + c));
                x[nt][0] += acc[nt][0] + bb.x; x[nt][1] += acc[nt][1] + bb.y;
                x[nt][2] += acc[nt][2] + bb.x; x[nt][3] += acc[nt][3] + bb.y;
            }
            ln_frag(x, ln1g + l * 64, ln1b + l * 64, j);
        }

        // -------- FF1 -> relu -> FF2 -> residual -> LN2 (all regs)
        {
            uint32_t fah[16], fal[16];
            pack_frags(x, fah, fal);
            float t1[8][4];
#pragma unroll
            for (int nt = 0; nt < 8; nt++) { t1[nt][0] = t1[nt][1] = t1[nt][2] = t1[nt][3] = 0.f; }
            gemm_pk<8>(fah, fal, wl + 4096, t1, r, j);
#pragma unroll
            for (int nt = 0; nt < 8; nt++) {
                int c = nt * 8 + j * 2;
                float2 bb = __ldg(reinterpret_cast<const float2*>(b1 + l * 64 + c));
                t1[nt][0] = fmaxf(t1[nt][0] + bb.x, 0.f); t1[nt][1] = fmaxf(t1[nt][1] + bb.y, 0.f);
                t1[nt][2] = fmaxf(t1[nt][2] + bb.x, 0.f); t1[nt][3] = fmaxf(t1[nt][3] + bb.y, 0.f);
            }
            uint32_t gah[16], gal[16];
            pack_frags(t1, gah, gal);
            float acc[8][4];
#pragma unroll
            for (int nt = 0; nt < 8; nt++) { acc[nt][0] = acc[nt][1] = acc[nt][2] = acc[nt][3] = 0.f; }
            gemm_pk<8>(gah, gal, wl + 5120, acc, r, j);
#pragma unroll
            for (int nt = 0; nt < 8; nt++) {
                int c = nt * 8 + j * 2;
                float2 bb = __ldg(reinterpret_cast<const float2*>(b2 + l * 64 + c));
                x[nt][0] += acc[nt][0] + bb.x; x[nt][1] += acc[nt][1] + bb.y;
                x[nt][2] += acc[nt][2] + bb.x; x[nt][3] += acc[nt][3] + bb.y;
            }
            ln_frag(x, ln2g + l * 64, ln2b + l * 64, j);
        }
    }

    // -------- final projection: out = x @ Wout + bout
    {
        uint32_t fah[16], fal[16];
        pack_frags(x, fah, fal);
        float acc[12][4];
#pragma unroll
        for (int nt = 0; nt < 12; nt++) { acc[nt][0] = acc[nt][1] = acc[nt][2] = acc[nt][3] = 0.f; }
        gemm_pk<12>(fah, fal, g_wpk + 24 * 1024, acc, r, j);
        float* o0 = out + (size_t)(blk * ROWS + m0 + r) * VOCAB;
        float* o1 = out + (size_t)(blk * ROWS + m0 + r + 8) * VOCAB;
#pragma unroll
        for (int nt = 0; nt < 12; nt++) {
            int c = nt * 8 + j * 2;
            float2 bb = __ldg(reinterpret_cast<const float2*>(bout + c));
            *reinterpret_cast<float2*>(o0 + c) = make_float2(acc[nt][0] + bb.x, acc[nt][1] + bb.y);
            *reinterpret_cast<float2*>(o1 + c) = make_float2(acc[nt][2] + bb.x, acc[nt][3] + bb.y);
        }
    }
}

extern "C" void kernel_launch(void* const* d_in, const int* in_sizes, int n_in,
                              void* d_out, int out_size) {
    const int*   data    = (const int*)d_in[0];
    const float* tok_emb = (const float*)d_in[1];
    const float* pos_emb = (const float*)d_in[2];
    const float* Wq      = (const float*)d_in[3];
    const float* Wk      = (const float*)d_in[4];
    const float* Wv      = (const float*)d_in[5];
    const float* Wo      = (const float*)d_in[6];
    const float* bo      = (const float*)d_in[7];
    const float* ln1g    = (const float*)d_in[8];
    const float* ln1b    = (const float*)d_in[9];
    const float* ln2g    = (const float*)d_in[10];
    const float* ln2b    = (const float*)d_in[11];
    const float* W1      = (const float*)d_in[12];
    const float* b1      = (const float*)d_in[13];
    const float* W2      = (const float*)d_in[14];
    const float* b2      = (const float*)d_in[15];
    const float* Wout    = (const float*)d_in[16];
    const float* bout    = (const float*)d_in[17];
    float* out = (float*)d_out;

    prep_kernel<<<(TOTAL_UNITS + 255) / 256, 256>>>(Wq, Wk, Wv, Wo, W1, W2, Wout);
    cudaFuncSetAttribute(bert_mma_kernel,
                         cudaFuncAttributeMaxDynamicSharedMemorySize, SMEM_BYTES);
    bert_mma_kernel<<<BB / G, NT, SMEM_BYTES>>>(
        data, tok_emb, pos_emb, bo, ln1g, ln1b, ln2g, ln2b,
        b1, b2, bout, out);
}

// round 12
// speedup vs baseline: 2.8493x; 1.0865x over previous
#include <cuda_runtime.h>
#include <cuda_bf16.h>
#include <cstdint>

#define VOCAB 96
#define TT 16
#define EE 64
#define LL 4
#define BB 16384
#define G 4
#define ROWS 64
#define NT 128

#define RS 144            // bf16 row stride bytes for QH/KH/XAH (72 bf16)
#define VSTR 72           // fp32 V row stride (floats)

// smem offsets (bytes) — all warp-private rows
#define O_XAH  0
#define O_QH   9216
#define O_KH   18432
#define O_VF   27648
#define SMEM_BYTES (O_VF + ROWS * VSTR * 4)   // 46080

#define TOTAL_UNITS (24 * 1024 + 1536)

__device__ __align__(16) uint4 g_wpk[TOTAL_UNITS];

// ---------------- helpers ----------------
__device__ __forceinline__ uint32_t phi(float a, float b) {
    __nv_bfloat162 t = __floats2bfloat162_rn(a, b);
    return *reinterpret_cast<uint32_t*>(&t);
}
__device__ __forceinline__ uint32_t plo(float a, float b, uint32_t h) {
    float2 f = __bfloat1622float2(*reinterpret_cast<__nv_bfloat162*>(&h));
    __nv_bfloat162 t = __floats2bfloat162_rn(a - f.x, b - f.y);
    return *reinterpret_cast<uint32_t*>(&t);
}
__device__ __forceinline__ void up2(uint32_t w, float* o) {
    float2 f = __bfloat1622float2(*reinterpret_cast<__nv_bfloat162*>(&w));
    o[0] = f.x; o[1] = f.y;
}
__device__ __forceinline__ void up8(const char* p, float* o) {
    uint4 u = *reinterpret_cast<const uint4*>(p);
    up2(u.x, o); up2(u.y, o + 2); up2(u.z, o + 4); up2(u.w, o + 6);
}
__device__ __forceinline__ void mma16816(float d[4], uint32_t a0, uint32_t a1,
                                         uint32_t a2, uint32_t a3,
                                         uint32_t b0, uint32_t b1) {
    asm volatile(
        "mma.sync.aligned.m16n8k16.row.col.f32.bf16.bf16.f32 "
        "{%0,%1,%2,%3}, {%4,%5,%6,%7}, {%8,%9}, {%0,%1,%2,%3};"
        : "+f"(d[0]), "+f"(d[1]), "+f"(d[2]), "+f"(d[3])
        : "r"(a0), "r"(a1), "r"(a2), "r"(a3), "r"(b0), "r"(b1));
}
// pack activation fragments, hi only (for 2-term internal GEMMs)
__device__ __forceinline__ void pack_hi_frags(const float act[8][4], uint32_t ah[16]) {
#pragma unroll
    for (int ks = 0; ks < 4; ks++) {
        const float* a0 = act[2 * ks];
        const float* a1 = act[2 * ks + 1];
        ah[4*ks+0] = phi(a0[0], a0[1]);
        ah[4*ks+1] = phi(a0[2], a0[3]);
        ah[4*ks+2] = phi(a1[0], a1[1]);
        ah[4*ks+3] = phi(a1[2], a1[3]);
    }
}
// pack hi+lo (final projection only)
__device__ __forceinline__ void pack_frags(const float act[8][4],
                                           uint32_t ah[16], uint32_t al[16]) {
#pragma unroll
    for (int ks = 0; ks < 4; ks++) {
        const float* a0 = act[2 * ks];
        const float* a1 = act[2 * ks + 1];
        ah[4*ks+0] = phi(a0[0], a0[1]); al[4*ks+0] = plo(a0[0], a0[1], ah[4*ks+0]);
        ah[4*ks+1] = phi(a0[2], a0[3]); al[4*ks+1] = plo(a0[2], a0[3], ah[4*ks+1]);
        ah[4*ks+2] = phi(a1[0], a1[1]); al[4*ks+2] = plo(a1[0], a1[1], ah[4*ks+2]);
        ah[4*ks+3] = phi(a1[2], a1[3]); al[4*ks+3] = plo(a1[2], a1[3], ah[4*ks+3]);
    }
}
// 2-term GEMM: A hi-only regs, B hi+lo from global: D += Ah*Bh + Ah*Bl
template <int NTL>
__device__ __forceinline__ void gemm2(const uint32_t ah[16],
                                      const uint4* __restrict__ wu,
                                      float acc[NTL][4], int r, int j) {
#pragma unroll
    for (int ks = 0; ks < 4; ks++) {
        const uint32_t* AH = ah + 4 * ks;
#pragma unroll
        for (int nt = 0; nt < NTL; nt++) {
            uint4 b = __ldg(wu + ((nt * 4 + ks) * 8 + r) * 4 + j);
            mma16816(acc[nt], AH[0], AH[1], AH[2], AH[3], b.x, b.y);
            mma16816(acc[nt], AH[0], AH[1], AH[2], AH[3], b.z, b.w);
        }
    }
}
// 3-term GEMM (final projection): D += Ah*Bh + Al*Bh + Ah*Bl
template <int NTL>
__device__ __forceinline__ void gemm3(const uint32_t ah[16], const uint32_t al[16],
                                      const uint4* __restrict__ wu,
                                      float acc[NTL][4], int r, int j) {
#pragma unroll
    for (int ks = 0; ks < 4; ks++) {
        const uint32_t* AH = ah + 4 * ks;
        const uint32_t* AL = al + 4 * ks;
#pragma unroll
        for (int nt = 0; nt < NTL; nt++) {
            uint4 b = __ldg(wu + ((nt * 4 + ks) * 8 + r) * 4 + j);
            mma16816(acc[nt], AH[0], AH[1], AH[2], AH[3], b.x, b.y);
            mma16816(acc[nt], AL[0], AL[1], AL[2], AL[3], b.x, b.y);
            mma16816(acc[nt], AH[0], AH[1], AH[2], AH[3], b.z, b.w);
        }
    }
}
// o @ Wo: A hi-only from smem, 2-term
__device__ __forceinline__ void gemm_o(const char* xah, const uint4* __restrict__ wu,
                                       float acc[8][4], int m0, int r, int j) {
#pragma unroll
    for (int ks = 0; ks < 4; ks++) {
        uint32_t off = (m0 + r) * RS + ks * 32 + j * 4;
        uint32_t a0 = *reinterpret_cast<const uint32_t*>(xah + off);
        uint32_t a1 = *reinterpret_cast<const uint32_t*>(xah + off + 8 * RS);
        uint32_t a2 = *reinterpret_cast<const uint32_t*>(xah + off + 16);
        uint32_t a3 = *reinterpret_cast<const uint32_t*>(xah + off + 8 * RS + 16);
#pragma unroll
        for (int nt = 0; nt < 8; nt++) {
            uint4 b = __ldg(wu + ((nt * 4 + ks) * 8 + r) * 4 + j);
            mma16816(acc[nt], a0, a1, a2, a3, b.x, b.y);
            mma16816(acc[nt], a0, a1, a2, a3, b.z, b.w);
        }
    }
}
__device__ __forceinline__ void fstore_hi(char* B, int m0, int r, int j,
                                          const float a[8][4]) {
#pragma unroll
    for (int nt = 0; nt < 8; nt++) {
        uint32_t co = (uint32_t)(nt * 16 + j * 4);
        *reinterpret_cast<uint32_t*>(B + (m0 + r) * RS + co) = phi(a[nt][0], a[nt][1]);
        *reinterpret_cast<uint32_t*>(B + (m0 + r + 8) * RS + co) = phi(a[nt][2], a[nt][3]);
    }
}
__device__ __forceinline__ void fstore_f32(float* V, int m0, int r, int j,
                                           const float a[8][4]) {
#pragma unroll
    for (int nt = 0; nt < 8; nt++) {
        int c = nt * 8 + j * 2;
        *reinterpret_cast<float2*>(V + (m0 + r) * VSTR + c) = make_float2(a[nt][0], a[nt][1]);
        *reinterpret_cast<float2*>(V + (m0 + r + 8) * VSTR + c) = make_float2(a[nt][2], a[nt][3]);
    }
}
__device__ __forceinline__ void ln_frag(float x[8][4], const float* __restrict__ g,
                                        const float* __restrict__ b, int j) {
    float s0 = 0.f, q0 = 0.f, s1 = 0.f, q1 = 0.f;
#pragma unroll
    for (int nt = 0; nt < 8; nt++) {
        s0 += x[nt][0] + x[nt][1]; q0 += x[nt][0] * x[nt][0] + x[nt][1] * x[nt][1];
        s1 += x[nt][2] + x[nt][3]; q1 += x[nt][2] * x[nt][2] + x[nt][3] * x[nt][3];
    }
    s0 += __shfl_xor_sync(0xffffffffu, s0, 1); q0 += __shfl_xor_sync(0xffffffffu, q0, 1);
    s1 += __shfl_xor_sync(0xffffffffu, s1, 1); q1 += __shfl_xor_sync(0xffffffffu, q1, 1);
    s0 += __shfl_xor_sync(0xffffffffu, s0, 2); q0 += __shfl_xor_sync(0xffffffffu, q0, 2);
    s1 += __shfl_xor_sync(0xffffffffu, s1, 2); q1 += __shfl_xor_sync(0xffffffffu, q1, 2);
    float m0 = s0 * (1.f / 64.f), m1 = s1 * (1.f / 64.f);
    float r0 = rsqrtf(q0 * (1.f / 64.f) - m0 * m0 + 1e-5f);
    float r1 = rsqrtf(q1 * (1.f / 64.f) - m1 * m1 + 1e-5f);
#pragma unroll
    for (int nt = 0; nt < 8; nt++) {
        int c = nt * 8 + j * 2;
        float2 gg = __ldg(reinterpret_cast<const float2*>(g + c));
        float2 bb = __ldg(reinterpret_cast<const float2*>(b + c));
        x[nt][0] = (x[nt][0] - m0) * r0 * gg.x + bb.x;
        x[nt][1] = (x[nt][1] - m0) * r0 * gg.y + bb.y;
        x[nt][2] = (x[nt][2] - m1) * r1 * gg.x + bb.x;
        x[nt][3] = (x[nt][3] - m1) * r1 * gg.y + bb.y;
    }
}

// ---------------- prep kernel: pack weight fragments ----------------
__global__ void prep_kernel(const float* __restrict__ Wq, const float* __restrict__ Wk,
                            const float* __restrict__ Wv, const float* __restrict__ Wo,
                            const float* __restrict__ W1, const float* __restrict__ W2,
                            const float* __restrict__ Wout) {
    int gid = blockIdx.x * 256 + threadIdx.x;
    if (gid >= TOTAL_UNITS) return;
    int u, c, k0;
    float v00, v01, v80, v81;
    if (gid < 24 * 1024) {
        int sidx = gid >> 10;
        u = gid & 1023;
        int l = sidx / 6, slot = sidx % 6;
        int nt = u >> 7, ks = (u >> 5) & 3, r = (u >> 2) & 7, j = u & 3;
        c = nt * 8 + r;
        k0 = ks * 16 + j * 2;
        if (slot < 3) {
            const float* W = (slot == 0) ? Wq : (slot == 1) ? Wk : Wv;
            const float* p = W + l * 4096 + (c >> 4) * 1024 + (c & 15);
            v00 = p[k0 * 16]; v01 = p[(k0 + 1) * 16];
            v80 = p[(k0 + 8) * 16]; v81 = p[(k0 + 9) * 16];
        } else {
            const float* W = (slot == 3) ? Wo : (slot == 4) ? W1 : W2;
            const float* p = W + l * 4096 + c;
            v00 = p[k0 * 64]; v01 = p[(k0 + 1) * 64];
            v80 = p[(k0 + 8) * 64]; v81 = p[(k0 + 9) * 64];
        }
    } else {
        u = gid - 24 * 1024;
        int nt = u >> 7, ks = (u >> 5) & 3, r = (u >> 2) & 7, j = u & 3;
        c = nt * 8 + r;
        k0 = ks * 16 + j * 2;
        const float* p = Wout + c;
        v00 = p[k0 * 96]; v01 = p[(k0 + 1) * 96];
        v80 = p[(k0 + 8) * 96]; v81 = p[(k0 + 9) * 96];
    }
    uint32_t h0 = phi(v00, v01), h8 = phi(v80, v81);
    uint32_t l0 = plo(v00, v01, h0), l8 = plo(v80, v81, h8);
    g_wpk[gid] = make_uint4(h0, h8, l0, l8);
}

// ---------------- main kernel: no __syncthreads, 4 CTAs/SM ----------------
__global__ void __launch_bounds__(NT, 4)
bert_mma_kernel(const int* __restrict__ data, const float* __restrict__ tok_emb,
                const float* __restrict__ pos_emb,
                const float* __restrict__ bo,
                const float* __restrict__ ln1g, const float* __restrict__ ln1b,
                const float* __restrict__ ln2g, const float* __restrict__ ln2b,
                const float* __restrict__ b1, const float* __restrict__ b2,
                const float* __restrict__ bout, float* __restrict__ out) {
    extern __shared__ char sm[];
    char* XAH = sm + O_XAH;
    char* QH = sm + O_QH;  char* KH = sm + O_KH;
    float* VF = reinterpret_cast<float*>(sm + O_VF);

    const int tid = threadIdx.x;
    const int w = tid >> 5, lane = tid & 31;
    const int r = lane >> 2, j = lane & 3;
    const int m0 = w * 16;
    const int blk = blockIdx.x;

    // -------- embedding (fragment layout)
    float x[8][4];
    {
        int b = blk * G + w;
        int tokA = data[b * TT + r], tokB = data[b * TT + r + 8];
#pragma unroll
        for (int nt = 0; nt < 8; nt++) {
            int c = nt * 8 + j * 2;
            float2 tA = __ldg(reinterpret_cast<const float2*>(tok_emb + tokA * EE + c));
            float2 tB = __ldg(reinterpret_cast<const float2*>(tok_emb + tokB * EE + c));
            float2 pA = __ldg(reinterpret_cast<const float2*>(pos_emb + r * EE + c));
            float2 pB = __ldg(reinterpret_cast<const float2*>(pos_emb + (r + 8) * EE + c));
            x[nt][0] = tA.x + pA.x; x[nt][1] = tA.y + pA.y;
            x[nt][2] = tB.x + pB.x; x[nt][3] = tB.y + pB.y;
        }
    }

    for (int l = 0; l < LL; l++) {
        const uint4* wl = g_wpk + l * 6 * 1024;

        // pack x (hi) once for Q/K/V
        uint32_t pah[16];
        pack_hi_frags(x, pah);

        {   // Q
            float acc[8][4];
#pragma unroll
            for (int nt = 0; nt < 8; nt++) { acc[nt][0] = acc[nt][1] = acc[nt][2] = acc[nt][3] = 0.f; }
            gemm2<8>(pah, wl + 0, acc, r, j);
            fstore_hi(QH, m0, r, j, acc);
        }
        {   // K
            float acc[8][4];
#pragma unroll
            for (int nt = 0; nt < 8; nt++) { acc[nt][0] = acc[nt][1] = acc[nt][2] = acc[nt][3] = 0.f; }
            gemm2<8>(pah, wl + 1024, acc, r, j);
            fstore_hi(KH, m0, r, j, acc);
        }
        {   // V
            float acc[8][4];
#pragma unroll
            for (int nt = 0; nt < 8; nt++) { acc[nt][0] = acc[nt][1] = acc[nt][2] = acc[nt][3] = 0.f; }
            gemm2<8>(pah, wl + 2048, acc, r, j);
            fstore_f32(VF, m0, r, j, acc);
        }
        __syncwarp();

        // -------- attention (warp-private rows)
#pragma unroll
        for (int it = 0; it < 2; it++) {
            int h = ((lane >> 4) << 1) | it;
            int t = lane & 15;
            int row = m0 + t;
            float q[16];
            up8(QH + row * RS + h * 32, q);
            up8(QH + row * RS + h * 32 + 16, q + 8);
            float p[16], mx = -1e30f;
#pragma unroll
            for (int s = 0; s < 16; s++) {
                float kk[16];
                up8(KH + (m0 + s) * RS + h * 32, kk);
                up8(KH + (m0 + s) * RS + h * 32 + 16, kk + 8);
                float a = 0.f;
#pragma unroll
                for (int i = 0; i < 16; i++) a += q[i] * kk[i];
                a *= 0.25f;
                p[s] = a; mx = fmaxf(mx, a);
            }
            float sum = 0.f;
#pragma unroll
            for (int s = 0; s < 16; s++) { p[s] = __expf(p[s] - mx); sum += p[s]; }
            float inv = 1.f / sum;
            float o[16];
#pragma unroll
            for (int i = 0; i < 16; i++) o[i] = 0.f;
#pragma unroll
            for (int s = 0; s < 16; s++) {
                const float4* v4 = reinterpret_cast<const float4*>(VF + (m0 + s) * VSTR + h * 16);
                float4 a0 = v4[0], a1 = v4[1], a2 = v4[2], a3 = v4[3];
                float ps = p[s];
                o[0] += ps * a0.x; o[1] += ps * a0.y; o[2] += ps * a0.z; o[3] += ps * a0.w;
                o[4] += ps * a1.x; o[5] += ps * a1.y; o[6] += ps * a1.z; o[7] += ps * a1.w;
                o[8] += ps * a2.x; o[9] += ps * a2.y; o[10] += ps * a2.z; o[11] += ps * a2.w;
                o[12] += ps * a3.x; o[13] += ps * a3.y; o[14] += ps * a3.z; o[15] += ps * a3.w;
            }
            uint32_t hw[8];
#pragma unroll
            for (int pz = 0; pz < 8; pz++)
                hw[pz] = phi(o[2 * pz] * inv, o[2 * pz + 1] * inv);
            char* dh = XAH + row * RS + h * 32;
            *reinterpret_cast<uint4*>(dh) = make_uint4(hw[0], hw[1], hw[2], hw[3]);
            *reinterpret_cast<uint4*>(dh + 16) = make_uint4(hw[4], hw[5], hw[6], hw[7]);
        }
        __syncwarp();

        // -------- o @ Wo + bo + x ; LN1
        {
            float acc[8][4];
#pragma unroll
            for (int nt = 0; nt < 8; nt++) { acc[nt][0] = acc[nt][1] = acc[nt][2] = acc[nt][3] = 0.f; }
            gemm_o(XAH, wl + 3072, acc, m0, r, j);
#pragma unroll
            for (int nt = 0; nt < 8; nt++) {
                int c = nt * 8 + j * 2;
                float2 bb = __ldg(reinterpret_cast<const float2*>(bo + l * 64 + c));
                x[nt][0] += acc[nt][0] + bb.x; x[nt][1] += acc[nt][1] + bb.y;
                x[nt][2] += acc[nt][2] + bb.x; x[nt][3] += acc[nt][3] + bb.y;
            }
            ln_frag(x, ln1g + l * 64, ln1b + l * 64, j);
        }

        // -------- FF1 -> relu -> FF2 -> residual -> LN2 (all regs)
        {
            uint32_t fah[16];
            pack_hi_frags(x, fah);
            float t1[8][4];
#pragma unroll
            for (int nt = 0; nt < 8; nt++) { t1[nt][0] = t1[nt][1] = t1[nt][2] = t1[nt][3] = 0.f; }
            gemm2<8>(fah, wl + 4096, t1, r, j);
#pragma unroll
            for (int nt = 0; nt < 8; nt++) {
                int c = nt * 8 + j * 2;
                float2 bb = __ldg(reinterpret_cast<const float2*>(b1 + l * 64 + c));
                t1[nt][0] = fmaxf(t1[nt][0] + bb.x, 0.f); t1[nt][1] = fmaxf(t1[nt][1] + bb.y, 0.f);
                t1[nt][2] = fmaxf(t1[nt][2] + bb.x, 0.f); t1[nt][3] = fmaxf(t1[nt][3] + bb.y, 0.f);
            }
            uint32_t gah[16];
            pack_hi_frags(t1, gah);
            float acc[8][4];
#pragma unroll
            for (int nt = 0; nt < 8; nt++) { acc[nt][0] = acc[nt][1] = acc[nt][2] = acc[nt][3] = 0.f; }
            gemm2<8>(gah, wl + 5120, acc, r, j);
#pragma unroll
            for (int nt = 0; nt < 8; nt++) {
                int c = nt * 8 + j * 2;
                float2 bb = __ldg(reinterpret_cast<const float2*>(b2 + l * 64 + c));
                x[nt][0] += acc[nt][0] + bb.x; x[nt][1] += acc[nt][1] + bb.y;
                x[nt][2] += acc[nt][2] + bb.x; x[nt][3] += acc[nt][3] + bb.y;
            }
            ln_frag(x, ln2g + l * 64, ln2b + l * 64, j);
        }
    }

    // -------- final projection: out = x @ Wout + bout (3-term, full precision)
    {
        uint32_t fah[16], fal[16];
        pack_frags(x, fah, fal);
        float acc[12][4];
#pragma unroll
        for (int nt = 0; nt < 12; nt++) { acc[nt][0] = acc[nt][1] = acc[nt][2] = acc[nt][3] = 0.f; }
        gemm3<12>(fah, fal, g_wpk + 24 * 1024, acc, r, j);
        float* o0 = out + (size_t)(blk * ROWS + m0 + r) * VOCAB;
        float* o1 = out + (size_t)(blk * ROWS + m0 + r + 8) * VOCAB;
#pragma unroll
        for (int nt = 0; nt < 12; nt++) {
            int c = nt * 8 + j * 2;
            float2 bb = __ldg(reinterpret_cast<const float2*>(bout + c));
            *reinterpret_cast<float2*>(o0 + c) = make_float2(acc[nt][0] + bb.x, acc[nt][1] + bb.y);
            *reinterpret_cast<float2*>(o1 + c) = make_float2(acc[nt][2] + bb.x, acc[nt][3] + bb.y);
        }
    }
}

extern "C" void kernel_launch(void* const* d_in, const int* in_sizes, int n_in,
                              void* d_out, int out_size) {
    const int*   data    = (const int*)d_in[0];
    const float* tok_emb = (const float*)d_in[1];
    const float* pos_emb = (const float*)d_in[2];
    const float* Wq      = (const float*)d_in[3];
    const float* Wk      = (const float*)d_in[4];
    const float* Wv      = (const float*)d_in[5];
    const float* Wo      = (const float*)d_in[6];
    const float* bo      = (const float*)d_in[7];
    const float* ln1g    = (const float*)d_in[8];
    const float* ln1b    = (const float*)d_in[9];
    const float* ln2g    = (const float*)d_in[10];
    const float* ln2b    = (const float*)d_in[11];
    const float* W1      = (const float*)d_in[12];
    const float* b1      = (const float*)d_in[13];
    const float* W2      = (const float*)d_in[14];
    const float* b2      = (const float*)d_in[15];
    const float* Wout    = (const float*)d_in[16];
    const float* bout    = (const float*)d_in[17];
    float* out = (float*)d_out;

    prep_kernel<<<(TOTAL_UNITS + 255) / 256, 256>>>(Wq, Wk, Wv, Wo, W1, W2, Wout);
    cudaFuncSetAttribute(bert_mma_kernel,
                         cudaFuncAttributeMaxDynamicSharedMemorySize, SMEM_BYTES);
    bert_mma_kernel<<<BB / G, NT, SMEM_BYTES>>>(
        data, tok_emb, pos_emb, bo, ln1g, ln1b, ln2g, ln2b,
        b1, b2, bout, out);
}

// round 13
// speedup vs baseline: 3.4138x; 1.1981x over previous
#include <cuda_runtime.h>
#include <cuda_bf16.h>
#include <cstdint>

#define VOCAB 96
#define TT 16
#define EE 64
#define LL 4
#define BB 16384
#define G 4
#define ROWS 64
#define NT 128

#define RS 144            // bf16 row stride bytes for KH
#define VTS 40            // VT row stride bytes (16 bf16 + pad)

// smem offsets (bytes) — all warp-private
#define O_KH   0
#define O_VT   9216
#define SMEM_BYTES (O_VT + 4 * 64 * VTS)   // 19456

#define TOTAL_UNITS (24 * 1024 + 1536)

__device__ __align__(16) uint4 g_wpk[TOTAL_UNITS];

// ---------------- helpers ----------------
__device__ __forceinline__ uint32_t phi(float a, float b) {
    __nv_bfloat162 t = __floats2bfloat162_rn(a, b);
    return *reinterpret_cast<uint32_t*>(&t);
}
__device__ __forceinline__ uint32_t plo(float a, float b, uint32_t h) {
    float2 f = __bfloat1622float2(*reinterpret_cast<__nv_bfloat162*>(&h));
    __nv_bfloat162 t = __floats2bfloat162_rn(a - f.x, b - f.y);
    return *reinterpret_cast<uint32_t*>(&t);
}
__device__ __forceinline__ void mma16816(float d[4], uint32_t a0, uint32_t a1,
                                         uint32_t a2, uint32_t a3,
                                         uint32_t b0, uint32_t b1) {
    asm volatile(
        "mma.sync.aligned.m16n8k16.row.col.f32.bf16.bf16.f32 "
        "{%0,%1,%2,%3}, {%4,%5,%6,%7}, {%8,%9}, {%0,%1,%2,%3};"
        : "+f"(d[0]), "+f"(d[1]), "+f"(d[2]), "+f"(d[3])
        : "r"(a0), "r"(a1), "r"(a2), "r"(a3), "r"(b0), "r"(b1));
}
__device__ __forceinline__ void pack_hi_frags(const float act[8][4], uint32_t ah[16]) {
#pragma unroll
    for (int ks = 0; ks < 4; ks++) {
        const float* a0 = act[2 * ks];
        const float* a1 = act[2 * ks + 1];
        ah[4*ks+0] = phi(a0[0], a0[1]);
        ah[4*ks+1] = phi(a0[2], a0[3]);
        ah[4*ks+2] = phi(a1[0], a1[1]);
        ah[4*ks+3] = phi(a1[2], a1[3]);
    }
}
__device__ __forceinline__ void pack_frags(const float act[8][4],
                                           uint32_t ah[16], uint32_t al[16]) {
#pragma unroll
    for (int ks = 0; ks < 4; ks++) {
        const float* a0 = act[2 * ks];
        const float* a1 = act[2 * ks + 1];
        ah[4*ks+0] = phi(a0[0], a0[1]); al[4*ks+0] = plo(a0[0], a0[1], ah[4*ks+0]);
        ah[4*ks+1] = phi(a0[2], a0[3]); al[4*ks+1] = plo(a0[2], a0[3], ah[4*ks+1]);
        ah[4*ks+2] = phi(a1[0], a1[1]); al[4*ks+2] = plo(a1[0], a1[1], ah[4*ks+2]);
        ah[4*ks+3] = phi(a1[2], a1[3]); al[4*ks+3] = plo(a1[2], a1[3], ah[4*ks+3]);
    }
}
// 2-term GEMM: A hi-only regs, B hi+lo from global
template <int NTL>
__device__ __forceinline__ void gemm2(const uint32_t ah[16],
                                      const uint4* __restrict__ wu,
                                      float acc[NTL][4], int r, int j) {
#pragma unroll
    for (int ks = 0; ks < 4; ks++) {
        const uint32_t* AH = ah + 4 * ks;
#pragma unroll
        for (int nt = 0; nt < NTL; nt++) {
            uint4 b = __ldg(wu + ((nt * 4 + ks) * 8 + r) * 4 + j);
            mma16816(acc[nt], AH[0], AH[1], AH[2], AH[3], b.x, b.y);
            mma16816(acc[nt], AH[0], AH[1], AH[2], AH[3], b.z, b.w);
        }
    }
}
// 3-term GEMM (final projection)
template <int NTL>
__device__ __forceinline__ void gemm3(const uint32_t ah[16], const uint32_t al[16],
                                      const uint4* __restrict__ wu,
                                      float acc[NTL][4], int r, int j) {
#pragma unroll
    for (int ks = 0; ks < 4; ks++) {
        const uint32_t* AH = ah + 4 * ks;
        const uint32_t* AL = al + 4 * ks;
#pragma unroll
        for (int nt = 0; nt < NTL; nt++) {
            uint4 b = __ldg(wu + ((nt * 4 + ks) * 8 + r) * 4 + j);
            mma16816(acc[nt], AH[0], AH[1], AH[2], AH[3], b.x, b.y);
            mma16816(acc[nt], AL[0], AL[1], AL[2], AL[3], b.x, b.y);
            mma16816(acc[nt], AH[0], AH[1], AH[2], AH[3], b.z, b.w);
        }
    }
}
__device__ __forceinline__ void fstore_hi(char* B, int m0, int r, int j,
                                          const float a[8][4]) {
#pragma unroll
    for (int nt = 0; nt < 8; nt++) {
        uint32_t co = (uint32_t)(nt * 16 + j * 4);
        *reinterpret_cast<uint32_t*>(B + (m0 + r) * RS + co) = phi(a[nt][0], a[nt][1]);
        *reinterpret_cast<uint32_t*>(B + (m0 + r + 8) * RS + co) = phi(a[nt][2], a[nt][3]);
    }
}
// store V transposed as bf16-hi: VT[c][s]
__device__ __forceinline__ void fstore_vt(char* vt, int r, int j, const float a[8][4]) {
#pragma unroll
    for (int nt = 0; nt < 8; nt++) {
        int c = nt * 8 + 2 * j;
        *reinterpret_cast<__nv_bfloat16*>(vt + c * VTS + r * 2) = __float2bfloat16(a[nt][0]);
        *reinterpret_cast<__nv_bfloat16*>(vt + (c + 1) * VTS + r * 2) = __float2bfloat16(a[nt][1]);
        *reinterpret_cast<__nv_bfloat16*>(vt + c * VTS + (r + 8) * 2) = __float2bfloat16(a[nt][2]);
        *reinterpret_cast<__nv_bfloat16*>(vt + (c + 1) * VTS + (r + 8) * 2) = __float2bfloat16(a[nt][3]);
    }
}
__device__ __forceinline__ void ln_frag(float x[8][4], const float* __restrict__ g,
                                        const float* __restrict__ b, int j) {
    float s0 = 0.f, q0 = 0.f, s1 = 0.f, q1 = 0.f;
#pragma unroll
    for (int nt = 0; nt < 8; nt++) {
        s0 += x[nt][0] + x[nt][1]; q0 += x[nt][0] * x[nt][0] + x[nt][1] * x[nt][1];
        s1 += x[nt][2] + x[nt][3]; q1 += x[nt][2] * x[nt][2] + x[nt][3] * x[nt][3];
    }
    s0 += __shfl_xor_sync(0xffffffffu, s0, 1); q0 += __shfl_xor_sync(0xffffffffu, q0, 1);
    s1 += __shfl_xor_sync(0xffffffffu, s1, 1); q1 += __shfl_xor_sync(0xffffffffu, q1, 1);
    s0 += __shfl_xor_sync(0xffffffffu, s0, 2); q0 += __shfl_xor_sync(0xffffffffu, q0, 2);
    s1 += __shfl_xor_sync(0xffffffffu, s1, 2); q1 += __shfl_xor_sync(0xffffffffu, q1, 2);
    float m0 = s0 * (1.f / 64.f), m1 = s1 * (1.f / 64.f);
    float r0 = rsqrtf(q0 * (1.f / 64.f) - m0 * m0 + 1e-5f);
    float r1 = rsqrtf(q1 * (1.f / 64.f) - m1 * m1 + 1e-5f);
#pragma unroll
    for (int nt = 0; nt < 8; nt++) {
        int c = nt * 8 + j * 2;
        float2 gg = __ldg(reinterpret_cast<const float2*>(g + c));
        float2 bb = __ldg(reinterpret_cast<const float2*>(b + c));
        x[nt][0] = (x[nt][0] - m0) * r0 * gg.x + bb.x;
        x[nt][1] = (x[nt][1] - m0) * r0 * gg.y + bb.y;
        x[nt][2] = (x[nt][2] - m1) * r1 * gg.x + bb.x;
        x[nt][3] = (x[nt][3] - m1) * r1 * gg.y + bb.y;
    }
}

// ---------------- prep kernel (unchanged layout) ----------------
__global__ void prep_kernel(const float* __restrict__ Wq, const float* __restrict__ Wk,
                            const float* __restrict__ Wv, const float* __restrict__ Wo,
                            const float* __restrict__ W1, const float* __restrict__ W2,
                            const float* __restrict__ Wout) {
    int gid = blockIdx.x * 256 + threadIdx.x;
    if (gid >= TOTAL_UNITS) return;
    int u, c, k0;
    float v00, v01, v80, v81;
    if (gid < 24 * 1024) {
        int sidx = gid >> 10;
        u = gid & 1023;
        int l = sidx / 6, slot = sidx % 6;
        int nt = u >> 7, ks = (u >> 5) & 3, r = (u >> 2) & 7, j = u & 3;
        c = nt * 8 + r;
        k0 = ks * 16 + j * 2;
        if (slot < 3) {
            const float* W = (slot == 0) ? Wq : (slot == 1) ? Wk : Wv;
            const float* p = W + l * 4096 + (c >> 4) * 1024 + (c & 15);
            v00 = p[k0 * 16]; v01 = p[(k0 + 1) * 16];
            v80 = p[(k0 + 8) * 16]; v81 = p[(k0 + 9) * 16];
        } else {
            const float* W = (slot == 3) ? Wo : (slot == 4) ? W1 : W2;
            const float* p = W + l * 4096 + c;
            v00 = p[k0 * 64]; v01 = p[(k0 + 1) * 64];
            v80 = p[(k0 + 8) * 64]; v81 = p[(k0 + 9) * 64];
        }
    } else {
        u = gid - 24 * 1024;
        int nt = u >> 7, ks = (u >> 5) & 3, r = (u >> 2) & 7, j = u & 3;
        c = nt * 8 + r;
        k0 = ks * 16 + j * 2;
        const float* p = Wout + c;
        v00 = p[k0 * 96]; v01 = p[(k0 + 1) * 96];
        v80 = p[(k0 + 8) * 96]; v81 = p[(k0 + 9) * 96];
    }
    uint32_t h0 = phi(v00, v01), h8 = phi(v80, v81);
    uint32_t l0 = plo(v00, v01, h0), l8 = plo(v80, v81, h8);
    g_wpk[gid] = make_uint4(h0, h8, l0, l8);
}

// ---------------- main kernel ----------------
__global__ void __launch_bounds__(NT, 4)
bert_mma_kernel(const int* __restrict__ data, const float* __restrict__ tok_emb,
                const float* __restrict__ pos_emb,
                const float* __restrict__ bo,
                const float* __restrict__ ln1g, const float* __restrict__ ln1b,
                const float* __restrict__ ln2g, const float* __restrict__ ln2b,
                const float* __restrict__ b1, const float* __restrict__ b2,
                const float* __restrict__ bout, float* __restrict__ out) {
    extern __shared__ char sm[];
    char* KH = sm + O_KH;

    const int tid = threadIdx.x;
    const int w = tid >> 5, lane = tid & 31;
    const int r = lane >> 2, j = lane & 3;   // r = groupID, j = lane%4
    const int m0 = w * 16;
    const int blk = blockIdx.x;
    char* vt = sm + O_VT + w * 64 * VTS;     // warp-private V^T

    // -------- embedding (fragment layout)
    float x[8][4];
    {
        int b = blk * G + w;
        int tokA = data[b * TT + r], tokB = data[b * TT + r + 8];
#pragma unroll
        for (int nt = 0; nt < 8; nt++) {
            int c = nt * 8 + j * 2;
            float2 tA = __ldg(reinterpret_cast<const float2*>(tok_emb + tokA * EE + c));
            float2 tB = __ldg(reinterpret_cast<const float2*>(tok_emb + tokB * EE + c));
            float2 pA = __ldg(reinterpret_cast<const float2*>(pos_emb + r * EE + c));
            float2 pB = __ldg(reinterpret_cast<const float2*>(pos_emb + (r + 8) * EE + c));
            x[nt][0] = tA.x + pA.x; x[nt][1] = tA.y + pA.y;
            x[nt][2] = tB.x + pB.x; x[nt][3] = tB.y + pB.y;
        }
    }

    for (int l = 0; l < LL; l++) {
        const uint4* wl = g_wpk + l * 6 * 1024;

        uint32_t pah[16];
        pack_hi_frags(x, pah);

        // Q -> registers (packed A-frags per head, pre-scaled by 1/sqrt(K)=0.25)
        uint32_t qa[16];
        {
            float acc[8][4];
#pragma unroll
            for (int nt = 0; nt < 8; nt++) { acc[nt][0] = acc[nt][1] = acc[nt][2] = acc[nt][3] = 0.f; }
            gemm2<8>(pah, wl + 0, acc, r, j);
#pragma unroll
            for (int h = 0; h < 4; h++) {
                qa[4*h+0] = phi(acc[2*h][0] * 0.25f, acc[2*h][1] * 0.25f);
                qa[4*h+1] = phi(acc[2*h][2] * 0.25f, acc[2*h][3] * 0.25f);
                qa[4*h+2] = phi(acc[2*h+1][0] * 0.25f, acc[2*h+1][1] * 0.25f);
                qa[4*h+3] = phi(acc[2*h+1][2] * 0.25f, acc[2*h+1][3] * 0.25f);
            }
        }
        // K -> smem rows (bf16 hi)
        {
            float acc[8][4];
#pragma unroll
            for (int nt = 0; nt < 8; nt++) { acc[nt][0] = acc[nt][1] = acc[nt][2] = acc[nt][3] = 0.f; }
            gemm2<8>(pah, wl + 1024, acc, r, j);
            fstore_hi(KH, m0, r, j, acc);
        }
        // V -> smem transposed (bf16 hi)
        {
            float acc[8][4];
#pragma unroll
            for (int nt = 0; nt < 8; nt++) { acc[nt][0] = acc[nt][1] = acc[nt][2] = acc[nt][3] = 0.f; }
            gemm2<8>(pah, wl + 2048, acc, r, j);
            fstore_vt(vt, r, j, acc);
        }
        __syncwarp();

        // -------- attention: fragment-native, o accumulated in registers
        uint32_t oa[16];
#pragma unroll
        for (int h = 0; h < 4; h++) {
            const uint32_t* q4 = qa + 4 * h;
            float s0[4] = {0.f, 0.f, 0.f, 0.f}, s1[4] = {0.f, 0.f, 0.f, 0.f};
            // S = Q K^T : B-frag from KH rows (n = s', k-pairs contiguous in e)
            {
                const char* k0p = KH + (m0 + r) * RS + h * 32;
                uint32_t b0 = *reinterpret_cast<const uint32_t*>(k0p + 4 * j);
                uint32_t b1 = *reinterpret_cast<const uint32_t*>(k0p + 16 + 4 * j);
                mma16816(s0, q4[0], q4[1], q4[2], q4[3], b0, b1);
                const char* k1p = KH + (m0 + 8 + r) * RS + h * 32;
                b0 = *reinterpret_cast<const uint32_t*>(k1p + 4 * j);
                b1 = *reinterpret_cast<const uint32_t*>(k1p + 16 + 4 * j);
                mma16816(s1, q4[0], q4[1], q4[2], q4[3], b0, b1);
            }
            // softmax: row r uses d0,d1 of both tiles; row r+8 uses d2,d3
            float mx0 = fmaxf(fmaxf(s0[0], s0[1]), fmaxf(s1[0], s1[1]));
            float mx1 = fmaxf(fmaxf(s0[2], s0[3]), fmaxf(s1[2], s1[3]));
            mx0 = fmaxf(mx0, __shfl_xor_sync(0xffffffffu, mx0, 1));
            mx0 = fmaxf(mx0, __shfl_xor_sync(0xffffffffu, mx0, 2));
            mx1 = fmaxf(mx1, __shfl_xor_sync(0xffffffffu, mx1, 1));
            mx1 = fmaxf(mx1, __shfl_xor_sync(0xffffffffu, mx1, 2));
            float e00 = __expf(s0[0] - mx0), e01 = __expf(s0[1] - mx0);
            float e10 = __expf(s1[0] - mx0), e11 = __expf(s1[1] - mx0);
            float f00 = __expf(s0[2] - mx1), f01 = __expf(s0[3] - mx1);
            float f10 = __expf(s1[2] - mx1), f11 = __expf(s1[3] - mx1);
            float sum0 = e00 + e01 + e10 + e11;
            float sum1 = f00 + f01 + f10 + f11;
            sum0 += __shfl_xor_sync(0xffffffffu, sum0, 1);
            sum0 += __shfl_xor_sync(0xffffffffu, sum0, 2);
            sum1 += __shfl_xor_sync(0xffffffffu, sum1, 1);
            sum1 += __shfl_xor_sync(0xffffffffu, sum1, 2);
            float iv0 = 1.f / sum0, iv1 = 1.f / sum1;
            // P A-frag (unnormalized)
            uint32_t p0 = phi(e00, e01);   // (r, s=2j,2j+1)
            uint32_t p1 = phi(f00, f01);   // (r+8, s=2j,2j+1)
            uint32_t p2 = phi(e10, e11);   // (r, s=2j+8,2j+9)
            uint32_t p3 = phi(f10, f11);   // (r+8, s=2j+8,2j+9)
            // O = P V : B-frag from VT rows (c = h*16 + n-tile*8 + r)
            float o0[4] = {0.f, 0.f, 0.f, 0.f}, o1[4] = {0.f, 0.f, 0.f, 0.f};
            {
                const char* v0p = vt + (h * 16 + r) * VTS;
                uint32_t b0 = *reinterpret_cast<const uint32_t*>(v0p + 4 * j);
                uint32_t b1 = *reinterpret_cast<const uint32_t*>(v0p + 16 + 4 * j);
                mma16816(o0, p0, p1, p2, p3, b0, b1);
                const char* v1p = vt + (h * 16 + 8 + r) * VTS;
                b0 = *reinterpret_cast<const uint32_t*>(v1p + 4 * j);
                b1 = *reinterpret_cast<const uint32_t*>(v1p + 16 + 4 * j);
                mma16816(o1, p0, p1, p2, p3, b0, b1);
            }
            // normalize + pack into Wo A-frag slot (k-step = h)
            oa[4*h+0] = phi(o0[0] * iv0, o0[1] * iv0);
            oa[4*h+1] = phi(o0[2] * iv1, o0[3] * iv1);
            oa[4*h+2] = phi(o1[0] * iv0, o1[1] * iv0);
            oa[4*h+3] = phi(o1[2] * iv1, o1[3] * iv1);
        }

        // -------- o @ Wo + bo + x ; LN1
        {
            float acc[8][4];
#pragma unroll
            for (int nt = 0; nt < 8; nt++) { acc[nt][0] = acc[nt][1] = acc[nt][2] = acc[nt][3] = 0.f; }
            gemm2<8>(oa, wl + 3072, acc, r, j);
#pragma unroll
            for (int nt = 0; nt < 8; nt++) {
                int c = nt * 8 + j * 2;
                float2 bb = __ldg(reinterpret_cast<const float2*>(bo + l * 64 + c));
                x[nt][0] += acc[nt][0] + bb.x; x[nt][1] += acc[nt][1] + bb.y;
                x[nt][2] += acc[nt][2] + bb.x; x[nt][3] += acc[nt][3] + bb.y;
            }
            ln_frag(x, ln1g + l * 64, ln1b + l * 64, j);
        }

        // -------- FF1 -> relu -> FF2 -> residual -> LN2 (all regs)
        {
            uint32_t fah[16];
            pack_hi_frags(x, fah);
            float t1[8][4];
#pragma unroll
            for (int nt = 0; nt < 8; nt++) { t1[nt][0] = t1[nt][1] = t1[nt][2] = t1[nt][3] = 0.f; }
            gemm2<8>(fah, wl + 4096, t1, r, j);
#pragma unroll
            for (int nt = 0; nt < 8; nt++) {
                int c = nt * 8 + j * 2;
                float2 bb = __ldg(reinterpret_cast<const float2*>(b1 + l * 64 + c));
                t1[nt][0] = fmaxf(t1[nt][0] + bb.x, 0.f); t1[nt][1] = fmaxf(t1[nt][1] + bb.y, 0.f);
                t1[nt][2] = fmaxf(t1[nt][2] + bb.x, 0.f); t1[nt][3] = fmaxf(t1[nt][3] + bb.y, 0.f);
            }
            uint32_t gah[16];
            pack_hi_frags(t1, gah);
            float acc[8][4];
#pragma unroll
            for (int nt = 0; nt < 8; nt++) { acc[nt][0] = acc[nt][1] = acc[nt][2] = acc[nt][3] = 0.f; }
            gemm2<8>(gah, wl + 5120, acc, r, j);
#pragma unroll
            for (int nt = 0; nt < 8; nt++) {
                int c = nt * 8 + j * 2;
                float2 bb = __ldg(reinterpret_cast<const float2*>(b2 + l * 64 + c));
                x[nt][0] += acc[nt][0] + bb.x; x[nt][1] += acc[nt][1] + bb.y;
                x[nt][2] += acc[nt][2] + bb.x; x[nt][3] += acc[nt][3] + bb.y;
            }
            ln_frag(x, ln2g + l * 64, ln2b + l * 64, j);
        }
    }

    // -------- final projection: out = x @ Wout + bout (3-term)
    {
        uint32_t fah[16], fal[16];
        pack_frags(x, fah, fal);
        float acc[12][4];
#pragma unroll
        for (int nt = 0; nt < 12; nt++) { acc[nt][0] = acc[nt][1] = acc[nt][2] = acc[nt][3] = 0.f; }
        gemm3<12>(fah, fal, g_wpk + 24 * 1024, acc, r, j);
        float* o0 = out + (size_t)(blk * ROWS + m0 + r) * VOCAB;
        float* o1 = out + (size_t)(blk * ROWS + m0 + r + 8) * VOCAB;
#pragma unroll
        for (int nt = 0; nt < 12; nt++) {
            int c = nt * 8 + j * 2;
            float2 bb = __ldg(reinterpret_cast<const float2*>(bout + c));
            *reinterpret_cast<float2*>(o0 + c) = make_float2(acc[nt][0] + bb.x, acc[nt][1] + bb.y);
            *reinterpret_cast<float2*>(o1 + c) = make_float2(acc[nt][2] + bb.x, acc[nt][3] + bb.y);
        }
    }
}

extern "C" void kernel_launch(void* const* d_in, const int* in_sizes, int n_in,
                              void* d_out, int out_size) {
    const int*   data    = (const int*)d_in[0];
    const float* tok_emb = (const float*)d_in[1];
    const float* pos_emb = (const float*)d_in[2];
    const float* Wq      = (const float*)d_in[3];
    const float* Wk      = (const float*)d_in[4];
    const float* Wv      = (const float*)d_in[5];
    const float* Wo      = (const float*)d_in[6];
    const float* bo      = (const float*)d_in[7];
    const float* ln1g    = (const float*)d_in[8];
    const float* ln1b    = (const float*)d_in[9];
    const float* ln2g    = (const float*)d_in[10];
    const float* ln2b    = (const float*)d_in[11];
    const float* W1      = (const float*)d_in[12];
    const float* b1      = (const float*)d_in[13];
    const float* W2      = (const float*)d_in[14];
    const float* b2      = (const float*)d_in[15];
    const float* Wout    = (const float*)d_in[16];
    const float* bout    = (const float*)d_in[17];
    float* out = (float*)d_out;

    prep_kernel<<<(TOTAL_UNITS + 255) / 256, 256>>>(Wq, Wk, Wv, Wo, W1, W2, Wout);
    cudaFuncSetAttribute(bert_mma_kernel,
                         cudaFuncAttributeMaxDynamicSharedMemorySize, SMEM_BYTES);
    bert_mma_kernel<<<BB / G, NT, SMEM_BYTES>>>(
        data, tok_emb, pos_emb, bo, ln1g, ln1b, ln2g, ln2b,
        b1, b2, bout, out);
}

// round 14
// speedup vs baseline: 6.0517x; 1.7727x over previous
#include <cuda_runtime.h>
#include <cuda_bf16.h>
#include <cstdint>

#define VOCAB 96
#define TT 16
#define EE 64
#define LL 4
#define BB 16384
#define G 4
#define ROWS 64
#define NT 128

#define RS 144            // bf16 row stride bytes for KH
#define VTS 40            // VT row stride bytes (16 bf16 + pad)

// smem offsets (bytes) — all warp-private
#define O_KH   0
#define O_VT   9216
#define SMEM_BYTES (O_VT + 4 * 64 * VTS)   // 19456

#define TOTAL_UNITS (24 * 1024 + 1536)

__device__ __align__(16) uint4 g_wpk[TOTAL_UNITS];   // hi+lo (final projection)
__device__ __align__(16) uint2 g_wph[24 * 1024];     // hi-only (internal GEMMs)

// ---------------- helpers ----------------
__device__ __forceinline__ uint32_t phi(float a, float b) {
    __nv_bfloat162 t = __floats2bfloat162_rn(a, b);
    return *reinterpret_cast<uint32_t*>(&t);
}
__device__ __forceinline__ uint32_t plo(float a, float b, uint32_t h) {
    float2 f = __bfloat1622float2(*reinterpret_cast<__nv_bfloat162*>(&h));
    __nv_bfloat162 t = __floats2bfloat162_rn(a - f.x, b - f.y);
    return *reinterpret_cast<uint32_t*>(&t);
}
__device__ __forceinline__ void mma16816(float d[4], uint32_t a0, uint32_t a1,
                                         uint32_t a2, uint32_t a3,
                                         uint32_t b0, uint32_t b1) {
    asm volatile(
        "mma.sync.aligned.m16n8k16.row.col.f32.bf16.bf16.f32 "
        "{%0,%1,%2,%3}, {%4,%5,%6,%7}, {%8,%9}, {%0,%1,%2,%3};"
        : "+f"(d[0]), "+f"(d[1]), "+f"(d[2]), "+f"(d[3])
        : "r"(a0), "r"(a1), "r"(a2), "r"(a3), "r"(b0), "r"(b1));
}
__device__ __forceinline__ void pack_hi_frags(const float act[8][4], uint32_t ah[16]) {
#pragma unroll
    for (int ks = 0; ks < 4; ks++) {
        const float* a0 = act[2 * ks];
        const float* a1 = act[2 * ks + 1];
        ah[4*ks+0] = phi(a0[0], a0[1]);
        ah[4*ks+1] = phi(a0[2], a0[3]);
        ah[4*ks+2] = phi(a1[0], a1[1]);
        ah[4*ks+3] = phi(a1[2], a1[3]);
    }
}
__device__ __forceinline__ void pack_frags(const float act[8][4],
                                           uint32_t ah[16], uint32_t al[16]) {
#pragma unroll
    for (int ks = 0; ks < 4; ks++) {
        const float* a0 = act[2 * ks];
        const float* a1 = act[2 * ks + 1];
        ah[4*ks+0] = phi(a0[0], a0[1]); al[4*ks+0] = plo(a0[0], a0[1], ah[4*ks+0]);
        ah[4*ks+1] = phi(a0[2], a0[3]); al[4*ks+1] = plo(a0[2], a0[3], ah[4*ks+1]);
        ah[4*ks+2] = phi(a1[0], a1[1]); al[4*ks+2] = plo(a1[0], a1[1], ah[4*ks+2]);
        ah[4*ks+3] = phi(a1[2], a1[3]); al[4*ks+3] = plo(a1[2], a1[3], ah[4*ks+3]);
    }
}
// 1-term GEMM: A hi regs, B hi-only from global
template <int NTL>
__device__ __forceinline__ void gemm1(const uint32_t ah[16],
                                      const uint2* __restrict__ wu,
                                      float acc[NTL][4], int r, int j) {
#pragma unroll
    for (int ks = 0; ks < 4; ks++) {
        const uint32_t* AH = ah + 4 * ks;
#pragma unroll
        for (int nt = 0; nt < NTL; nt++) {
            uint2 b = __ldg(wu + ((nt * 4 + ks) * 8 + r) * 4 + j);
            mma16816(acc[nt], AH[0], AH[1], AH[2], AH[3], b.x, b.y);
        }
    }
}
// 3-term GEMM (final projection)
template <int NTL>
__device__ __forceinline__ void gemm3(const uint32_t ah[16], const uint32_t al[16],
                                      const uint4* __restrict__ wu,
                                      float acc[NTL][4], int r, int j) {
#pragma unroll
    for (int ks = 0; ks < 4; ks++) {
        const uint32_t* AH = ah + 4 * ks;
        const uint32_t* AL = al + 4 * ks;
#pragma unroll
        for (int nt = 0; nt < NTL; nt++) {
            uint4 b = __ldg(wu + ((nt * 4 + ks) * 8 + r) * 4 + j);
            mma16816(acc[nt], AH[0], AH[1], AH[2], AH[3], b.x, b.y);
            mma16816(acc[nt], AL[0], AL[1], AL[2], AL[3], b.x, b.y);
            mma16816(acc[nt], AH[0], AH[1], AH[2], AH[3], b.z, b.w);
        }
    }
}
__device__ __forceinline__ void fstore_hi(char* B, int m0, int r, int j,
                                          const float a[8][4]) {
#pragma unroll
    for (int nt = 0; nt < 8; nt++) {
        uint32_t co = (uint32_t)(nt * 16 + j * 4);
        *reinterpret_cast<uint32_t*>(B + (m0 + r) * RS + co) = phi(a[nt][0], a[nt][1]);
        *reinterpret_cast<uint32_t*>(B + (m0 + r + 8) * RS + co) = phi(a[nt][2], a[nt][3]);
    }
}
__device__ __forceinline__ void fstore_vt(char* vt, int r, int j, const float a[8][4]) {
#pragma unroll
    for (int nt = 0; nt < 8; nt++) {
        int c = nt * 8 + 2 * j;
        *reinterpret_cast<__nv_bfloat16*>(vt + c * VTS + r * 2) = __float2bfloat16(a[nt][0]);
        *reinterpret_cast<__nv_bfloat16*>(vt + (c + 1) * VTS + r * 2) = __float2bfloat16(a[nt][1]);
        *reinterpret_cast<__nv_bfloat16*>(vt + c * VTS + (r + 8) * 2) = __float2bfloat16(a[nt][2]);
        *reinterpret_cast<__nv_bfloat16*>(vt + (c + 1) * VTS + (r + 8) * 2) = __float2bfloat16(a[nt][3]);
    }
}
__device__ __forceinline__ void ln_frag(float x[8][4], const float* __restrict__ g,
                                        const float* __restrict__ b, int j) {
    float s0 = 0.f, q0 = 0.f, s1 = 0.f, q1 = 0.f;
#pragma unroll
    for (int nt = 0; nt < 8; nt++) {
        s0 += x[nt][0] + x[nt][1]; q0 += x[nt][0] * x[nt][0] + x[nt][1] * x[nt][1];
        s1 += x[nt][2] + x[nt][3]; q1 += x[nt][2] * x[nt][2] + x[nt][3] * x[nt][3];
    }
    s0 += __shfl_xor_sync(0xffffffffu, s0, 1); q0 += __shfl_xor_sync(0xffffffffu, q0, 1);
    s1 += __shfl_xor_sync(0xffffffffu, s1, 1); q1 += __shfl_xor_sync(0xffffffffu, q1, 1);
    s0 += __shfl_xor_sync(0xffffffffu, s0, 2); q0 += __shfl_xor_sync(0xffffffffu, q0, 2);
    s1 += __shfl_xor_sync(0xffffffffu, s1, 2); q1 += __shfl_xor_sync(0xffffffffu, q1, 2);
    float m0 = s0 * (1.f / 64.f), m1 = s1 * (1.f / 64.f);
    float r0 = rsqrtf(q0 * (1.f / 64.f) - m0 * m0 + 1e-5f);
    float r1 = rsqrtf(q1 * (1.f / 64.f) - m1 * m1 + 1e-5f);
#pragma unroll
    for (int nt = 0; nt < 8; nt++) {
        int c = nt * 8 + j * 2;
        float2 gg = __ldg(reinterpret_cast<const float2*>(g + c));
        float2 bb = __ldg(reinterpret_cast<const float2*>(b + c));
        x[nt][0] = (x[nt][0] - m0) * r0 * gg.x + bb.x;
        x[nt][1] = (x[nt][1] - m0) * r0 * gg.y + bb.y;
        x[nt][2] = (x[nt][2] - m1) * r1 * gg.x + bb.x;
        x[nt][3] = (x[nt][3] - m1) * r1 * gg.y + bb.y;
    }
}

// ---------------- prep kernel ----------------
__global__ void prep_kernel(const float* __restrict__ Wq, const float* __restrict__ Wk,
                            const float* __restrict__ Wv, const float* __restrict__ Wo,
                            const float* __restrict__ W1, const float* __restrict__ W2,
                            const float* __restrict__ Wout) {
    int gid = blockIdx.x * 256 + threadIdx.x;
    if (gid >= TOTAL_UNITS) return;
    int u, c, k0;
    float v00, v01, v80, v81;
    if (gid < 24 * 1024) {
        int sidx = gid >> 10;
        u = gid & 1023;
        int l = sidx / 6, slot = sidx % 6;
        int nt = u >> 7, ks = (u >> 5) & 3, r = (u >> 2) & 7, j = u & 3;
        c = nt * 8 + r;
        k0 = ks * 16 + j * 2;
        if (slot < 3) {
            const float* W = (slot == 0) ? Wq : (slot == 1) ? Wk : Wv;
            const float* p = W + l * 4096 + (c >> 4) * 1024 + (c & 15);
            v00 = p[k0 * 16]; v01 = p[(k0 + 1) * 16];
            v80 = p[(k0 + 8) * 16]; v81 = p[(k0 + 9) * 16];
        } else {
            const float* W = (slot == 3) ? Wo : (slot == 4) ? W1 : W2;
            const float* p = W + l * 4096 + c;
            v00 = p[k0 * 64]; v01 = p[(k0 + 1) * 64];
            v80 = p[(k0 + 8) * 64]; v81 = p[(k0 + 9) * 64];
        }
    } else {
        u = gid - 24 * 1024;
        int nt = u >> 7, ks = (u >> 5) & 3, r = (u >> 2) & 7, j = u & 3;
        c = nt * 8 + r;
        k0 = ks * 16 + j * 2;
        const float* p = Wout + c;
        v00 = p[k0 * 96]; v01 = p[(k0 + 1) * 96];
        v80 = p[(k0 + 8) * 96]; v81 = p[(k0 + 9) * 96];
    }
    uint32_t h0 = phi(v00, v01), h8 = phi(v80, v81);
    uint32_t l0 = plo(v00, v01, h0), l8 = plo(v80, v81, h8);
    g_wpk[gid] = make_uint4(h0, h8, l0, l8);
    if (gid < 24 * 1024) g_wph[gid] = make_uint2(h0, h8);
}

// ---------------- main kernel ----------------
__global__ void __launch_bounds__(NT, 4)
bert_mma_kernel(const int* __restrict__ data, const float* __restrict__ tok_emb,
                const float* __restrict__ pos_emb,
                const float* __restrict__ bo,
                const float* __restrict__ ln1g, const float* __restrict__ ln1b,
                const float* __restrict__ ln2g, const float* __restrict__ ln2b,
                const float* __restrict__ b1, const float* __restrict__ b2,
                const float* __restrict__ bout, float* __restrict__ out) {
    extern __shared__ char sm[];
    char* KH = sm + O_KH;

    const int tid = threadIdx.x;
    const int w = tid >> 5, lane = tid & 31;
    const int r = lane >> 2, j = lane & 3;
    const int m0 = w * 16;
    const int blk = blockIdx.x;
    char* vt = sm + O_VT + w * 64 * VTS;

    // -------- embedding (fragment layout)
    float x[8][4];
    {
        int b = blk * G + w;
        int tokA = data[b * TT + r], tokB = data[b * TT + r + 8];
#pragma unroll
        for (int nt = 0; nt < 8; nt++) {
            int c = nt * 8 + j * 2;
            float2 tA = __ldg(reinterpret_cast<const float2*>(tok_emb + tokA * EE + c));
            float2 tB = __ldg(reinterpret_cast<const float2*>(tok_emb + tokB * EE + c));
            float2 pA = __ldg(reinterpret_cast<const float2*>(pos_emb + r * EE + c));
            float2 pB = __ldg(reinterpret_cast<const float2*>(pos_emb + (r + 8) * EE + c));
            x[nt][0] = tA.x + pA.x; x[nt][1] = tA.y + pA.y;
            x[nt][2] = tB.x + pB.x; x[nt][3] = tB.y + pB.y;
        }
    }

    for (int l = 0; l < LL; l++) {
        const uint2* wl = g_wph + l * 6 * 1024;

        uint32_t pah[16];
        pack_hi_frags(x, pah);

        // Q -> registers (A-frags per head, pre-scaled)
        uint32_t qa[16];
        {
            float acc[8][4];
#pragma unroll
            for (int nt = 0; nt < 8; nt++) { acc[nt][0] = acc[nt][1] = acc[nt][2] = acc[nt][3] = 0.f; }
            gemm1<8>(pah, wl + 0, acc, r, j);
#pragma unroll
            for (int h = 0; h < 4; h++) {
                qa[4*h+0] = phi(acc[2*h][0] * 0.25f, acc[2*h][1] * 0.25f);
                qa[4*h+1] = phi(acc[2*h][2] * 0.25f, acc[2*h][3] * 0.25f);
                qa[4*h+2] = phi(acc[2*h+1][0] * 0.25f, acc[2*h+1][1] * 0.25f);
                qa[4*h+3] = phi(acc[2*h+1][2] * 0.25f, acc[2*h+1][3] * 0.25f);
            }
        }
        // K -> smem rows (bf16 hi)
        {
            float acc[8][4];
#pragma unroll
            for (int nt = 0; nt < 8; nt++) { acc[nt][0] = acc[nt][1] = acc[nt][2] = acc[nt][3] = 0.f; }
            gemm1<8>(pah, wl + 1024, acc, r, j);
            fstore_hi(KH, m0, r, j, acc);
        }
        // V -> smem transposed (bf16 hi)
        {
            float acc[8][4];
#pragma unroll
            for (int nt = 0; nt < 8; nt++) { acc[nt][0] = acc[nt][1] = acc[nt][2] = acc[nt][3] = 0.f; }
            gemm1<8>(pah, wl + 2048, acc, r, j);
            fstore_vt(vt, r, j, acc);
        }
        __syncwarp();

        // -------- attention: fragment-native
        uint32_t oa[16];
#pragma unroll
        for (int h = 0; h < 4; h++) {
            const uint32_t* q4 = qa + 4 * h;
            float s0[4] = {0.f, 0.f, 0.f, 0.f}, s1[4] = {0.f, 0.f, 0.f, 0.f};
            {
                const char* k0p = KH + (m0 + r) * RS + h * 32;
                uint32_t b0 = *reinterpret_cast<const uint32_t*>(k0p + 4 * j);
                uint32_t b1 = *reinterpret_cast<const uint32_t*>(k0p + 16 + 4 * j);
                mma16816(s0, q4[0], q4[1], q4[2], q4[3], b0, b1);
                const char* k1p = KH + (m0 + 8 + r) * RS + h * 32;
                b0 = *reinterpret_cast<const uint32_t*>(k1p + 4 * j);
                b1 = *reinterpret_cast<const uint32_t*>(k1p + 16 + 4 * j);
                mma16816(s1, q4[0], q4[1], q4[2], q4[3], b0, b1);
            }
            float mx0 = fmaxf(fmaxf(s0[0], s0[1]), fmaxf(s1[0], s1[1]));
            float mx1 = fmaxf(fmaxf(s0[2], s0[3]), fmaxf(s1[2], s1[3]));
            mx0 = fmaxf(mx0, __shfl_xor_sync(0xffffffffu, mx0, 1));
            mx0 = fmaxf(mx0, __shfl_xor_sync(0xffffffffu, mx0, 2));
            mx1 = fmaxf(mx1, __shfl_xor_sync(0xffffffffu, mx1, 1));
            mx1 = fmaxf(mx1, __shfl_xor_sync(0xffffffffu, mx1, 2));
            float e00 = __expf(s0[0] - mx0), e01 = __expf(s0[1] - mx0);
            float e10 = __expf(s1[0] - mx0), e11 = __expf(s1[1] - mx0);
            float f00 = __expf(s0[2] - mx1), f01 = __expf(s0[3] - mx1);
            float f10 = __expf(s1[2] - mx1), f11 = __expf(s1[3] - mx1);
            float sum0 = e00 + e01 + e10 + e11;
            float sum1 = f00 + f01 + f10 + f11;
            sum0 += __shfl_xor_sync(0xffffffffu, sum0, 1);
            sum0 += __shfl_xor_sync(0xffffffffu, sum0, 2);
            sum1 += __shfl_xor_sync(0xffffffffu, sum1, 1);
            sum1 += __shfl_xor_sync(0xffffffffu, sum1, 2);
            float iv0 = 1.f / sum0, iv1 = 1.f / sum1;
            uint32_t p0 = phi(e00, e01);
            uint32_t p1 = phi(f00, f01);
            uint32_t p2 = phi(e10, e11);
            uint32_t p3 = phi(f10, f11);
            float o0[4] = {0.f, 0.f, 0.f, 0.f}, o1[4] = {0.f, 0.f, 0.f, 0.f};
            {
                const char* v0p = vt + (h * 16 + r) * VTS;
                uint32_t b0 = *reinterpret_cast<const uint32_t*>(v0p + 4 * j);
                uint32_t b1 = *reinterpret_cast<const uint32_t*>(v0p + 16 + 4 * j);
                mma16816(o0, p0, p1, p2, p3, b0, b1);
                const char* v1p = vt + (h * 16 + 8 + r) * VTS;
                b0 = *reinterpret_cast<const uint32_t*>(v1p + 4 * j);
                b1 = *reinterpret_cast<const uint32_t*>(v1p + 16 + 4 * j);
                mma16816(o1, p0, p1, p2, p3, b0, b1);
            }
            oa[4*h+0] = phi(o0[0] * iv0, o0[1] * iv0);
            oa[4*h+1] = phi(o0[2] * iv1, o0[3] * iv1);
            oa[4*h+2] = phi(o1[0] * iv0, o1[1] * iv0);
            oa[4*h+3] = phi(o1[2] * iv1, o1[3] * iv1);
        }

        // -------- o @ Wo + bo + x ; LN1
        {
            float acc[8][4];
#pragma unroll
            for (int nt = 0; nt < 8; nt++) { acc[nt][0] = acc[nt][1] = acc[nt][2] = acc[nt][3] = 0.f; }
            gemm1<8>(oa, wl + 3072, acc, r, j);
#pragma unroll
            for (int nt = 0; nt < 8; nt++) {
                int c = nt * 8 + j * 2;
                float2 bb = __ldg(reinterpret_cast<const float2*>(bo + l * 64 + c));
                x[nt][0] += acc[nt][0] + bb.x; x[nt][1] += acc[nt][1] + bb.y;
                x[nt][2] += acc[nt][2] + bb.x; x[nt][3] += acc[nt][3] + bb.y;
            }
            ln_frag(x, ln1g + l * 64, ln1b + l * 64, j);
        }

        // -------- FF1 -> relu -> FF2 -> residual -> LN2
        {
            uint32_t fah[16];
            pack_hi_frags(x, fah);
            float t1[8][4];
#pragma unroll
            for (int nt = 0; nt < 8; nt++) { t1[nt][0] = t1[nt][1] = t1[nt][2] = t1[nt][3] = 0.f; }
            gemm1<8>(fah, wl + 4096, t1, r, j);
#pragma unroll
            for (int nt = 0; nt < 8; nt++) {
                int c = nt * 8 + j * 2;
                float2 bb = __ldg(reinterpret_cast<const float2*>(b1 + l * 64 + c));
                t1[nt][0] = fmaxf(t1[nt][0] + bb.x, 0.f); t1[nt][1] = fmaxf(t1[nt][1] + bb.y, 0.f);
                t1[nt][2] = fmaxf(t1[nt][2] + bb.x, 0.f); t1[nt][3] = fmaxf(t1[nt][3] + bb.y, 0.f);
            }
            uint32_t gah[16];
            pack_hi_frags(t1, gah);
            float acc[8][4];
#pragma unroll
            for (int nt = 0; nt < 8; nt++) { acc[nt][0] = acc[nt][1] = acc[nt][2] = acc[nt][3] = 0.f; }
            gemm1<8>(gah, wl + 5120, acc, r, j);
#pragma unroll
            for (int nt = 0; nt < 8; nt++) {
                int c = nt * 8 + j * 2;
                float2 bb = __ldg(reinterpret_cast<const float2*>(b2 + l * 64 + c));
                x[nt][0] += acc[nt][0] + bb.x; x[nt][1] += acc[nt][1] + bb.y;
                x[nt][2] += acc[nt][2] + bb.x; x[nt][3] += acc[nt][3] + bb.y;
            }
            ln_frag(x, ln2g + l * 64, ln2b + l * 64, j);
        }
    }

    // -------- final projection: out = x @ Wout + bout (3-term)
    {
        uint32_t fah[16], fal[16];
        pack_frags(x, fah, fal);
        float acc[12][4];
#pragma unroll
        for (int nt = 0; nt < 12; nt++) { acc[nt][0] = acc[nt][1] = acc[nt][2] = acc[nt][3] = 0.f; }
        gemm3<12>(fah, fal, g_wpk + 24 * 1024, acc, r, j);
        float* o0 = out + (size_t)(blk * ROWS + m0 + r) * VOCAB;
        float* o1 = out + (size_t)(blk * ROWS + m0 + r + 8) * VOCAB;
#pragma unroll
        for (int nt = 0; nt < 12; nt++) {
            int c = nt * 8 + j * 2;
            float2 bb = __ldg(reinterpret_cast<const float2*>(bout + c));
            *reinterpret_cast<float2*>(o0 + c) = make_float2(acc[nt][0] + bb.x, acc[nt][1] + bb.y);
            *reinterpret_cast<float2*>(o1 + c) = make_float2(acc[nt][2] + bb.x, acc[nt][3] + bb.y);
        }
    }
}

extern "C" void kernel_launch(void* const* d_in, const int* in_sizes, int n_in,
                              void* d_out, int out_size) {
    const int*   data    = (const int*)d_in[0];
    const float* tok_emb = (const float*)d_in[1];
    const float* pos_emb = (const float*)d_in[2];
    const float* Wq      = (const float*)d_in[3];
    const float* Wk      = (const float*)d_in[4];
    const float* Wv      = (const float*)d_in[5];
    const float* Wo      = (const float*)d_in[6];
    const float* bo      = (const float*)d_in[7];
    const float* ln1g    = (const float*)d_in[8];
    const float* ln1b    = (const float*)d_in[9];
    const float* ln2g    = (const float*)d_in[10];
    const float* ln2b    = (const float*)d_in[11];
    const float* W1      = (const float*)d_in[12];
    const float* b1      = (const float*)d_in[13];
    const float* W2      = (const float*)d_in[14];
    const float* b2      = (const float*)d_in[15];
    const float* Wout    = (const float*)d_in[16];
    const float* bout    = (const float*)d_in[17];
    float* out = (float*)d_out;

    prep_kernel<<<(TOTAL_UNITS + 255) / 256, 256>>>(Wq, Wk, Wv, Wo, W1, W2, Wout);
    cudaFuncSetAttribute(bert_mma_kernel,
                         cudaFuncAttributeMaxDynamicSharedMemorySize, SMEM_BYTES);
    bert_mma_kernel<<<BB / G, NT, SMEM_BYTES>>>(
        data, tok_emb, pos_emb, bo, ln1g, ln1b, ln2g, ln2b,
        b1, b2, bout, out);
}